// round 12
// baseline (speedup 1.0000x reference)
#include <cuda_runtime.h>
#include <cuda_bf16.h>
#include <cuda_fp16.h>
#include <cstdint>

#define IN_DIM 128
#define HID    256
#define NU 100000
#define NI 200000
#define NTILE_U ((NU + 127) / 128)   // 782
#define NTILE_I ((NI + 127) / 128)   // 1563
#define KEXT 384                     // B: [Wh ; Wl ; Wh]

#define P_ELEMS (100000u * 256u)
#define Q_ELEMS (200000u * 256u)
__device__ __half g_tab[2u * (P_ELEMS + Q_ELEMS)];
__device__ __align__(16) __nv_bfloat16 g_wext[4][HID * KEXT];

// ---------------------------------------------------------------------------
__device__ __forceinline__ uint32_t smem_u32(const void* p) {
    uint32_t a;
    asm("{ .reg .u64 t; cvta.to.shared.u64 t, %1; cvt.u32.u64 %0, t; }"
        : "=r"(a) : "l"(p));
    return a;
}
__device__ __forceinline__ uint32_t swz(uint32_t o) { return o ^ ((o >> 3) & 0x70); }
__device__ __forceinline__ uint32_t pack2(float a, float b) {
    __nv_bfloat162 t = __floats2bfloat162_rn(a, b);
    return *(uint32_t*)&t;
}
template <int N>
__device__ __forceinline__ void cpwait() {
    asm volatile("cp.async.wait_group %0;" :: "n"(N) : "memory");
}

// ---------------------------------------------------------------------------
// convW (4 combos in one launch): W-half [128 k][256 n] -> [Wh | Wl | Wh]
// ---------------------------------------------------------------------------
__global__ __launch_bounds__(256)
void convW_kernel(const float* __restrict__ Wc, const float* __restrict__ Wb,
                  __nv_bfloat16* __restrict__ wext) {
    const int combo = blockIdx.y;
    const float* Wsrc = ((combo < 2) ? Wc : Wb) + (size_t)(combo & 1) * IN_DIM * HID;
    __nv_bfloat16* Wext = wext + (size_t)combo * HID * KEXT;
    for (int idx = blockIdx.x * 256 + threadIdx.x; idx < HID * IN_DIM;
         idx += gridDim.x * 256) {
        const int n = idx >> 7, k = idx & 127;
        const float x = Wsrc[(size_t)k * HID + n];
        const __nv_bfloat16 h = __float2bfloat16_rn(x);
        const float l = x - __bfloat162float(h);
        __nv_bfloat16* row = Wext + (size_t)n * KEXT;
        row[k]       = h;
        row[128 + k] = __float2bfloat16_rn(l);
        row[256 + k] = h;
    }
}

// ---------------------------------------------------------------------------
// persistent fused gemm, 1024 threads = 32 warps (8m x 4n), warp tile 16x64.
// fp32 A staged + tile-top conversion to [Ah|Al]; A prefetch at it==0;
// B double-buffered. smem: Astage 64KB | Aconv 64KB | B0 32KB | B1 32KB.
// ---------------------------------------------------------------------------
#define KC 64
#define GT 1024
#define SM_STAGE 0
#define SM_ACONV 65536
#define SM_B_OFF (2 * 65536)
#define GEMM_SMEM (SM_B_OFF + 2 * 32768)

__device__ __forceinline__ void ldsm4(uint32_t* r, uint32_t a) {
    asm volatile("ldmatrix.sync.aligned.m8n8.x4.shared.b16 {%0,%1,%2,%3}, [%4];"
                 : "=r"(r[0]), "=r"(r[1]), "=r"(r[2]), "=r"(r[3]) : "r"(a));
}
__device__ __forceinline__ void mma16816(float* d, const uint32_t* a,
                                         uint32_t b0, uint32_t b1) {
    asm volatile("mma.sync.aligned.m16n8k16.row.col.f32.bf16.bf16.f32 "
                 "{%0,%1,%2,%3}, {%4,%5,%6,%7}, {%8,%9}, {%0,%1,%2,%3};"
                 : "+f"(d[0]), "+f"(d[1]), "+f"(d[2]), "+f"(d[3])
                 : "r"(a[0]), "r"(a[1]), "r"(a[2]), "r"(a[3]), "r"(b0), "r"(b1));
}

__global__ __launch_bounds__(GT, 1)
void gemm_kernel(const float* __restrict__ A, int ntiles, int N,
                 const __nv_bfloat16* __restrict__ W0,
                 const __nv_bfloat16* __restrict__ W1,
                 const float* __restrict__ b1_0, const float* __restrict__ b1_1,
                 __half* __restrict__ P0, __half* __restrict__ P1) {
    extern __shared__ __align__(1024) unsigned char sm[];
    const uint32_t sbase = smem_u32(sm);
    const int tid  = threadIdx.x;
    const int lane = tid & 31;
    const int wid  = tid >> 5;     // 0..31
    const int wm   = wid & 7;      // 0..7  (16 rows each)
    const int wn   = wid >> 3;     // 0..3  (64 cols each)

    auto issue_b = [&](int it) {
        const char* Bb = (const char*)((it < 6) ? W0 : W1);
        const int c = it % 6;
        const uint32_t sb = sbase + SM_B_OFF + (uint32_t)(it & 1) * 32768;
        #pragma unroll
        for (int i = 0; i < 2; i++) {
            const int idx = tid + i * GT;
            const int r = idx >> 3, s = idx & 7;
            const size_t go = (size_t)r * (KEXT * 2) + c * (KC * 2) + s * 16;
            const uint32_t so = swz((uint32_t)(r * 128 + s * 16));
            asm volatile("cp.async.cg.shared.global [%0], [%1], 16;"
                         :: "r"(sb + so), "l"(Bb + go) : "memory");
        }
        asm volatile("cp.async.commit_group;" ::: "memory");
    };
    auto issue_a = [&](int t) {
        const float* Ab = A + (size_t)t * 128 * IN_DIM;
        const uint32_t sa = sbase + SM_STAGE;
        #pragma unroll
        for (int i = 0; i < 4; i++) {
            const int idx = tid + i * GT;
            const int r = idx >> 5, s = idx & 31;
            const int rg = t * 128 + r;
            const uint32_t so = (uint32_t)(r * 512 + s * 16);
            if (rg < N) {
                asm volatile("cp.async.cg.shared.global [%0], [%1], 16;"
                             :: "r"(sa + so), "l"((const char*)Ab + (size_t)r * 512 + s * 16)
                             : "memory");
            } else {
                *(uint4*)(sm + SM_STAGE + so) = make_uint4(0, 0, 0, 0);
            }
        }
        asm volatile("cp.async.commit_group;" ::: "memory");
    };
    auto convert_a = [&]() {
        #pragma unroll
        for (int i = 0; i < 4; i++) {
            const int idx = tid + i * GT;
            const int r = idx >> 5, c4 = idx & 31;
            float4 v = *(float4*)(sm + SM_STAGE + r * 512 + c4 * 16);
            float h0 = __bfloat162float(__float2bfloat16_rn(v.x));
            float h1 = __bfloat162float(__float2bfloat16_rn(v.y));
            float h2 = __bfloat162float(__float2bfloat16_rn(v.z));
            float h3 = __bfloat162float(__float2bfloat16_rn(v.w));
            uint2 uh = { pack2(h0, h1), pack2(h2, h3) };
            uint2 ul = { pack2(v.x - h0, v.y - h1), pack2(v.z - h2, v.w - h3) };
            const uint32_t ck = (uint32_t)(c4 >> 4);
            const uint32_t off = swz((uint32_t)(r * 128 + (c4 & 15) * 8));
            *(uint2*)(sm + SM_ACONV + ck * 16384 + off)         = uh;
            *(uint2*)(sm + SM_ACONV + 32768 + ck * 16384 + off) = ul;
        }
    };

    float acc[8][4];
    #pragma unroll
    for (int nt = 0; nt < 8; nt++)
        #pragma unroll
        for (int j = 0; j < 4; j++) acc[nt][j] = 0.f;

    const int t0 = blockIdx.x;
    if (t0 >= ntiles) return;

    issue_a(t0);
    issue_b(0);

    const int amap[6] = {0, 1, 0, 1, 2, 3};

    for (int t = t0; t < ntiles; t += gridDim.x) {
        const int tnext = t + gridDim.x;
        const bool a_iss = (tnext < ntiles);

        cpwait<1>();
        __syncthreads();
        convert_a();
        __syncthreads();

        #pragma unroll
        for (int it = 0; it < 12; it++) {
            const bool last_all = (it == 11) && !a_iss;
            if (!last_all) issue_b((it + 1) % 12);
            if (it == 0 && a_iss) issue_a(tnext);

            if (last_all)                cpwait<0>();
            else if (it < 2 && a_iss)    cpwait<2>();
            else                         cpwait<1>();
            __syncthreads();

            const uint32_t sa = sbase + SM_ACONV + (uint32_t)(amap[it % 6] * 16384);
            const uint32_t sb = sbase + SM_B_OFF + (uint32_t)(it & 1) * 32768;

            #pragma unroll
            for (int ks = 0; ks < KC / 16; ks++) {
                uint32_t af[4];
                {
                    const int row = wm * 16 + (lane & 15);
                    const uint32_t off = (uint32_t)(row * 128 + ks * 32 + (lane >> 4) * 16);
                    ldsm4(af, sa + swz(off));
                }
                #pragma unroll
                for (int ntp = 0; ntp < 4; ntp++) {
                    const int nrow = wn * 64 + ntp * 16 + ((lane >> 4) << 3) + (lane & 7);
                    const uint32_t off = (uint32_t)(nrow * 128 + ks * 32 + ((lane >> 3) & 1) * 16);
                    uint32_t r4[4];
                    ldsm4(r4, sb + swz(off));
                    mma16816(acc[2 * ntp],     af, r4[0], r4[1]);
                    mma16816(acc[2 * ntp + 1], af, r4[2], r4[3]);
                }
            }
            __syncthreads();

            if (it == 5 || it == 11) {
                __half* Pt = (it == 5) ? P0 : P1;
                const float* b1 = (it == 5) ? b1_0 : b1_1;
                const int rb = t * 128 + wm * 16 + (lane >> 2);
                const int cb = wn * 64 + (lane & 3) * 2;
                #pragma unroll
                for (int hf = 0; hf < 2; hf++) {
                    const int r = rb + hf * 8;
                    if (r < N) {
                        __half* dst = Pt + (size_t)r * HID + cb;
                        #pragma unroll
                        for (int nt = 0; nt < 8; nt++) {
                            const int c = cb + nt * 8;
                            float a0 = acc[nt][hf * 2]     + __ldg(b1 + c);
                            float a1 = acc[nt][hf * 2 + 1] + __ldg(b1 + c + 1);
                            *(__half2*)(dst + nt * 8) = __floats2half2_rn(a0, a1);
                        }
                    }
                }
                #pragma unroll
                for (int nt = 0; nt < 8; nt++)
                    #pragma unroll
                    for (int j = 0; j < 4; j++) acc[nt][j] = 0.f;
            }
        }
    }
}

// ---------------------------------------------------------------------------
// edge: persistent warps; W2/b2 in registers; 3 edges in flight per warp.
// ---------------------------------------------------------------------------
__global__ __launch_bounds__(256, 5)
void edge_kernel(const int* __restrict__ uc, const int* __restrict__ vc,
                 const int* __restrict__ ub, const int* __restrict__ vb,
                 const __half* __restrict__ Pc, const __half* __restrict__ Qc,
                 const __half* __restrict__ Pb, const __half* __restrict__ Qb,
                 const float4* __restrict__ W2c, const float* __restrict__ b2c,
                 const float4* __restrict__ W2b, const float* __restrict__ b2b,
                 float* __restrict__ out, int E, int wpt) {
    const int gw   = (blockIdx.x * blockDim.x + threadIdx.x) >> 5;
    const int lane = threadIdx.x & 31;
    const bool buys = (gw >= wpt);
    const int w0 = buys ? gw - wpt : gw;

    const int* uu = buys ? ub : uc;
    const int* vv = buys ? vb : vc;
    const __half* P = buys ? Pb : Pc;
    const __half* Q = buys ? Qb : Qc;
    const float4* W2 = buys ? W2b : W2c;
    float* o = out + (buys ? E : 0);

    float4 wv0 = __ldg(W2 + lane * 2);
    float4 wv1 = __ldg(W2 + lane * 2 + 1);
    const float b2v = __ldg(buys ? b2b : b2c);
    float w[8] = { wv0.x, wv0.y, wv0.z, wv0.w, wv1.x, wv1.y, wv1.z, wv1.w };

    auto dot8 = [&](const uint4& pr, const uint4& qr) -> float {
        const __half2* p2 = (const __half2*)&pr;
        const __half2* q2 = (const __half2*)&qr;
        float a = 0.f;
        #pragma unroll
        for (int i = 0; i < 4; i++) {
            float2 pf = __half22float2(p2[i]);
            float2 qf = __half22float2(q2[i]);
            a = fmaf(fmaxf(pf.x + qf.x, 0.f), w[2 * i],     a);
            a = fmaf(fmaxf(pf.y + qf.y, 0.f), w[2 * i + 1], a);
        }
        return a;
    };

    int e = w0;
    for (; e + 2 * wpt < E; e += 3 * wpt) {
        const int u0 = __ldg(uu + e),           v0 = __ldg(vv + e);
        const int u1 = __ldg(uu + e + wpt),     v1 = __ldg(vv + e + wpt);
        const int u2 = __ldg(uu + e + 2 * wpt), v2 = __ldg(vv + e + 2 * wpt);
        uint4 pr0 = *(const uint4*)(P + (size_t)u0 * HID + lane * 8);
        uint4 qr0 = *(const uint4*)(Q + (size_t)v0 * HID + lane * 8);
        uint4 pr1 = *(const uint4*)(P + (size_t)u1 * HID + lane * 8);
        uint4 qr1 = *(const uint4*)(Q + (size_t)v1 * HID + lane * 8);
        uint4 pr2 = *(const uint4*)(P + (size_t)u2 * HID + lane * 8);
        uint4 qr2 = *(const uint4*)(Q + (size_t)v2 * HID + lane * 8);
        float a0 = dot8(pr0, qr0);
        float a1 = dot8(pr1, qr1);
        float a2 = dot8(pr2, qr2);
        #pragma unroll
        for (int off = 16; off; off >>= 1) {
            a0 += __shfl_xor_sync(0xffffffffu, a0, off);
            a1 += __shfl_xor_sync(0xffffffffu, a1, off);
            a2 += __shfl_xor_sync(0xffffffffu, a2, off);
        }
        if (lane == 0) {
            o[e] = a0 + b2v;
            o[e + wpt] = a1 + b2v;
            o[e + 2 * wpt] = a2 + b2v;
        }
    }
    for (; e < E; e += wpt) {
        const int u0 = __ldg(uu + e), v0 = __ldg(vv + e);
        uint4 pr0 = *(const uint4*)(P + (size_t)u0 * HID + lane * 8);
        uint4 qr0 = *(const uint4*)(Q + (size_t)v0 * HID + lane * 8);
        float a0 = dot8(pr0, qr0);
        #pragma unroll
        for (int off = 16; off; off >>= 1)
            a0 += __shfl_xor_sync(0xffffffffu, a0, off);
        if (lane == 0) o[e] = a0 + b2v;
    }
}

// ---------------------------------------------------------------------------
extern "C" void kernel_launch(void* const* d_in, const int* in_sizes, int n_in,
                              void* d_out, int out_size) {
    const float* user_embed = (const float*)d_in[0];
    const float* item_embed = (const float*)d_in[1];
    const int*   u_clicks   = (const int*)  d_in[2];
    const int*   v_clicks   = (const int*)  d_in[3];
    const int*   u_buys     = (const int*)  d_in[4];
    const int*   v_buys     = (const int*)  d_in[5];
    const float* W1_clicks  = (const float*)d_in[6];
    const float* b1_clicks  = (const float*)d_in[7];
    const float* W2_clicks  = (const float*)d_in[8];
    const float* b2_clicks  = (const float*)d_in[9];
    const float* W1_buys    = (const float*)d_in[10];
    const float* b1_buys    = (const float*)d_in[11];
    const float* W2_buys    = (const float*)d_in[12];
    const float* b2_buys    = (const float*)d_in[13];

    const int E = in_sizes[2];
    float* out = (float*)d_out;

    __half* tab = nullptr;
    cudaGetSymbolAddress((void**)&tab, g_tab);
    __half* Pc = tab;
    __half* Qc = Pc + P_ELEMS;
    __half* Pb = Qc + Q_ELEMS;
    __half* Qb = Pb + P_ELEMS;

    __nv_bfloat16* wext = nullptr;
    cudaGetSymbolAddress((void**)&wext, g_wext);

    static bool attr_set = false;
    if (!attr_set) {
        cudaFuncSetAttribute(gemm_kernel,
                             cudaFuncAttributeMaxDynamicSharedMemorySize, GEMM_SMEM);
        attr_set = true;
    }

    const size_t wstride = (size_t)HID * KEXT;
    convW_kernel<<<dim3(16, 4), 256>>>(W1_clicks, W1_buys, wext);

    const int gU = NTILE_U < 148 ? NTILE_U : 148;
    const int gI = NTILE_I < 148 ? NTILE_I : 148;
    gemm_kernel<<<gU, GT, GEMM_SMEM>>>(user_embed, NTILE_U, NU,
                                       wext + 0 * wstride, wext + 2 * wstride,
                                       b1_clicks, b1_buys, Pc, Pb);
    gemm_kernel<<<gI, GT, GEMM_SMEM>>>(item_embed, NTILE_I, NI,
                                       wext + 1 * wstride, wext + 3 * wstride,
                                       b1_clicks, b1_buys, Qc, Qb);

    const int eblocks = 740;                       // 5 CTAs/SM
    const int wpt = eblocks * 8 / 2;               // 2960 warps per task
    edge_kernel<<<eblocks, 256>>>(u_clicks, v_clicks, u_buys, v_buys,
                                  Pc, Qc, Pb, Qb,
                                  (const float4*)W2_clicks, b2_clicks,
                                  (const float4*)W2_buys, b2_buys,
                                  out, E, wpt);
}

// round 13
// speedup vs baseline: 1.0001x; 1.0001x over previous
#include <cuda_runtime.h>
#include <cuda_bf16.h>
#include <cuda_fp16.h>
#include <cstdint>

#define IN_DIM 128
#define HID    256
#define NU 100000
#define NI 200000
#define NTILE_U ((NU + 127) / 128)   // 782
#define NTILE_I ((NI + 127) / 128)   // 1563
#define KEXT 384                     // B: [Wh ; Wl ; Wh]

#define P_ELEMS (100000u * 256u)
#define Q_ELEMS (200000u * 256u)
__device__ __half g_tab[2u * (P_ELEMS + Q_ELEMS)];
__device__ __align__(16) __nv_bfloat16 g_wext[4][HID * KEXT];

// ---------------------------------------------------------------------------
__device__ __forceinline__ uint32_t smem_u32(const void* p) {
    uint32_t a;
    asm("{ .reg .u64 t; cvta.to.shared.u64 t, %1; cvt.u32.u64 %0, t; }"
        : "=r"(a) : "l"(p));
    return a;
}
__device__ __forceinline__ uint32_t swz(uint32_t o) { return o ^ ((o >> 3) & 0x70); }
__device__ __forceinline__ uint32_t pack2(float a, float b) {
    __nv_bfloat162 t = __floats2bfloat162_rn(a, b);
    return *(uint32_t*)&t;
}
template <int N>
__device__ __forceinline__ void cpwait() {
    asm volatile("cp.async.wait_group %0;" :: "n"(N) : "memory");
}

// ---------------------------------------------------------------------------
// convW (4 combos in one launch): W-half [128 k][256 n] -> [Wh | Wl | Wh]
// ---------------------------------------------------------------------------
__global__ __launch_bounds__(256)
void convW_kernel(const float* __restrict__ Wc, const float* __restrict__ Wb,
                  __nv_bfloat16* __restrict__ wext) {
    const int combo = blockIdx.y;
    const float* Wsrc = ((combo < 2) ? Wc : Wb) + (size_t)(combo & 1) * IN_DIM * HID;
    __nv_bfloat16* Wext = wext + (size_t)combo * HID * KEXT;
    for (int idx = blockIdx.x * 256 + threadIdx.x; idx < HID * IN_DIM;
         idx += gridDim.x * 256) {
        const int n = idx >> 7, k = idx & 127;
        const float x = Wsrc[(size_t)k * HID + n];
        const __nv_bfloat16 h = __float2bfloat16_rn(x);
        const float l = x - __bfloat162float(h);
        __nv_bfloat16* row = Wext + (size_t)n * KEXT;
        row[k]       = h;
        row[128 + k] = __float2bfloat16_rn(l);
        row[256 + k] = h;
    }
}

// ---------------------------------------------------------------------------
// persistent fused gemm, 1024 threads = 32 warps (8m x 4n), warp tile 16x64.
// fp32 A staged + tile-top conversion to [Ah|Al]; A prefetch at it==0;
// B double-buffered. smem: Astage 64KB | Aconv 64KB | B0 32KB | B1 32KB.
// ---------------------------------------------------------------------------
#define KC 64
#define GT 1024
#define SM_STAGE 0
#define SM_ACONV 65536
#define SM_B_OFF (2 * 65536)
#define GEMM_SMEM (SM_B_OFF + 2 * 32768)

__device__ __forceinline__ void ldsm4(uint32_t* r, uint32_t a) {
    asm volatile("ldmatrix.sync.aligned.m8n8.x4.shared.b16 {%0,%1,%2,%3}, [%4];"
                 : "=r"(r[0]), "=r"(r[1]), "=r"(r[2]), "=r"(r[3]) : "r"(a));
}
__device__ __forceinline__ void mma16816(float* d, const uint32_t* a,
                                         uint32_t b0, uint32_t b1) {
    asm volatile("mma.sync.aligned.m16n8k16.row.col.f32.bf16.bf16.f32 "
                 "{%0,%1,%2,%3}, {%4,%5,%6,%7}, {%8,%9}, {%0,%1,%2,%3};"
                 : "+f"(d[0]), "+f"(d[1]), "+f"(d[2]), "+f"(d[3])
                 : "r"(a[0]), "r"(a[1]), "r"(a[2]), "r"(a[3]), "r"(b0), "r"(b1));
}

__global__ __launch_bounds__(GT, 1)
void gemm_kernel(const float* __restrict__ A, int ntiles, int N,
                 const __nv_bfloat16* __restrict__ W0,
                 const __nv_bfloat16* __restrict__ W1,
                 const float* __restrict__ b1_0, const float* __restrict__ b1_1,
                 __half* __restrict__ P0, __half* __restrict__ P1) {
    extern __shared__ __align__(1024) unsigned char sm[];
    const uint32_t sbase = smem_u32(sm);
    const int tid  = threadIdx.x;
    const int lane = tid & 31;
    const int wid  = tid >> 5;     // 0..31
    const int wm   = wid & 7;      // 0..7  (16 rows each)
    const int wn   = wid >> 3;     // 0..3  (64 cols each)

    auto issue_b = [&](int it) {
        const char* Bb = (const char*)((it < 6) ? W0 : W1);
        const int c = it % 6;
        const uint32_t sb = sbase + SM_B_OFF + (uint32_t)(it & 1) * 32768;
        #pragma unroll
        for (int i = 0; i < 2; i++) {
            const int idx = tid + i * GT;
            const int r = idx >> 3, s = idx & 7;
            const size_t go = (size_t)r * (KEXT * 2) + c * (KC * 2) + s * 16;
            const uint32_t so = swz((uint32_t)(r * 128 + s * 16));
            asm volatile("cp.async.cg.shared.global [%0], [%1], 16;"
                         :: "r"(sb + so), "l"(Bb + go) : "memory");
        }
        asm volatile("cp.async.commit_group;" ::: "memory");
    };
    auto issue_a = [&](int t) {
        const float* Ab = A + (size_t)t * 128 * IN_DIM;
        const uint32_t sa = sbase + SM_STAGE;
        #pragma unroll
        for (int i = 0; i < 4; i++) {
            const int idx = tid + i * GT;
            const int r = idx >> 5, s = idx & 31;
            const int rg = t * 128 + r;
            const uint32_t so = (uint32_t)(r * 512 + s * 16);
            if (rg < N) {
                asm volatile("cp.async.cg.shared.global [%0], [%1], 16;"
                             :: "r"(sa + so), "l"((const char*)Ab + (size_t)r * 512 + s * 16)
                             : "memory");
            } else {
                *(uint4*)(sm + SM_STAGE + so) = make_uint4(0, 0, 0, 0);
            }
        }
        asm volatile("cp.async.commit_group;" ::: "memory");
    };
    auto convert_a = [&]() {
        #pragma unroll
        for (int i = 0; i < 4; i++) {
            const int idx = tid + i * GT;
            const int r = idx >> 5, c4 = idx & 31;
            float4 v = *(float4*)(sm + SM_STAGE + r * 512 + c4 * 16);
            float h0 = __bfloat162float(__float2bfloat16_rn(v.x));
            float h1 = __bfloat162float(__float2bfloat16_rn(v.y));
            float h2 = __bfloat162float(__float2bfloat16_rn(v.z));
            float h3 = __bfloat162float(__float2bfloat16_rn(v.w));
            uint2 uh = { pack2(h0, h1), pack2(h2, h3) };
            uint2 ul = { pack2(v.x - h0, v.y - h1), pack2(v.z - h2, v.w - h3) };
            const uint32_t ck = (uint32_t)(c4 >> 4);
            const uint32_t off = swz((uint32_t)(r * 128 + (c4 & 15) * 8));
            *(uint2*)(sm + SM_ACONV + ck * 16384 + off)         = uh;
            *(uint2*)(sm + SM_ACONV + 32768 + ck * 16384 + off) = ul;
        }
    };

    float acc[8][4];
    #pragma unroll
    for (int nt = 0; nt < 8; nt++)
        #pragma unroll
        for (int j = 0; j < 4; j++) acc[nt][j] = 0.f;

    const int t0 = blockIdx.x;
    if (t0 >= ntiles) return;

    issue_a(t0);
    issue_b(0);

    const int amap[6] = {0, 1, 0, 1, 2, 3};

    for (int t = t0; t < ntiles; t += gridDim.x) {
        const int tnext = t + gridDim.x;
        const bool a_iss = (tnext < ntiles);

        cpwait<1>();
        __syncthreads();
        convert_a();
        __syncthreads();

        #pragma unroll
        for (int it = 0; it < 12; it++) {
            const bool last_all = (it == 11) && !a_iss;
            if (!last_all) issue_b((it + 1) % 12);
            if (it == 0 && a_iss) issue_a(tnext);

            if (last_all)                cpwait<0>();
            else if (it < 2 && a_iss)    cpwait<2>();
            else                         cpwait<1>();
            __syncthreads();

            const uint32_t sa = sbase + SM_ACONV + (uint32_t)(amap[it % 6] * 16384);
            const uint32_t sb = sbase + SM_B_OFF + (uint32_t)(it & 1) * 32768;

            #pragma unroll
            for (int ks = 0; ks < KC / 16; ks++) {
                uint32_t af[4];
                {
                    const int row = wm * 16 + (lane & 15);
                    const uint32_t off = (uint32_t)(row * 128 + ks * 32 + (lane >> 4) * 16);
                    ldsm4(af, sa + swz(off));
                }
                #pragma unroll
                for (int ntp = 0; ntp < 4; ntp++) {
                    const int nrow = wn * 64 + ntp * 16 + ((lane >> 4) << 3) + (lane & 7);
                    const uint32_t off = (uint32_t)(nrow * 128 + ks * 32 + ((lane >> 3) & 1) * 16);
                    uint32_t r4[4];
                    ldsm4(r4, sb + swz(off));
                    mma16816(acc[2 * ntp],     af, r4[0], r4[1]);
                    mma16816(acc[2 * ntp + 1], af, r4[2], r4[3]);
                }
            }
            __syncthreads();

            if (it == 5 || it == 11) {
                __half* Pt = (it == 5) ? P0 : P1;
                const float* b1 = (it == 5) ? b1_0 : b1_1;
                const int rb = t * 128 + wm * 16 + (lane >> 2);
                const int cb = wn * 64 + (lane & 3) * 2;
                #pragma unroll
                for (int hf = 0; hf < 2; hf++) {
                    const int r = rb + hf * 8;
                    if (r < N) {
                        __half* dst = Pt + (size_t)r * HID + cb;
                        #pragma unroll
                        for (int nt = 0; nt < 8; nt++) {
                            const int c = cb + nt * 8;
                            float a0 = acc[nt][hf * 2]     + __ldg(b1 + c);
                            float a1 = acc[nt][hf * 2 + 1] + __ldg(b1 + c + 1);
                            *(__half2*)(dst + nt * 8) = __floats2half2_rn(a0, a1);
                        }
                    }
                }
                #pragma unroll
                for (int nt = 0; nt < 8; nt++)
                    #pragma unroll
                    for (int j = 0; j < 4; j++) acc[nt][j] = 0.f;
            }
        }
    }
}

// ---------------------------------------------------------------------------
// edge: persistent warps; W2/b2 in registers; 3 edges in flight per warp.
// ---------------------------------------------------------------------------
__global__ __launch_bounds__(256, 5)
void edge_kernel(const int* __restrict__ uc, const int* __restrict__ vc,
                 const int* __restrict__ ub, const int* __restrict__ vb,
                 const __half* __restrict__ Pc, const __half* __restrict__ Qc,
                 const __half* __restrict__ Pb, const __half* __restrict__ Qb,
                 const float4* __restrict__ W2c, const float* __restrict__ b2c,
                 const float4* __restrict__ W2b, const float* __restrict__ b2b,
                 float* __restrict__ out, int E, int wpt) {
    const int gw   = (blockIdx.x * blockDim.x + threadIdx.x) >> 5;
    const int lane = threadIdx.x & 31;
    const bool buys = (gw >= wpt);
    const int w0 = buys ? gw - wpt : gw;

    const int* uu = buys ? ub : uc;
    const int* vv = buys ? vb : vc;
    const __half* P = buys ? Pb : Pc;
    const __half* Q = buys ? Qb : Qc;
    const float4* W2 = buys ? W2b : W2c;
    float* o = out + (buys ? E : 0);

    float4 wv0 = __ldg(W2 + lane * 2);
    float4 wv1 = __ldg(W2 + lane * 2 + 1);
    const float b2v = __ldg(buys ? b2b : b2c);
    float w[8] = { wv0.x, wv0.y, wv0.z, wv0.w, wv1.x, wv1.y, wv1.z, wv1.w };

    auto dot8 = [&](const uint4& pr, const uint4& qr) -> float {
        const __half2* p2 = (const __half2*)&pr;
        const __half2* q2 = (const __half2*)&qr;
        float a = 0.f;
        #pragma unroll
        for (int i = 0; i < 4; i++) {
            float2 pf = __half22float2(p2[i]);
            float2 qf = __half22float2(q2[i]);
            a = fmaf(fmaxf(pf.x + qf.x, 0.f), w[2 * i],     a);
            a = fmaf(fmaxf(pf.y + qf.y, 0.f), w[2 * i + 1], a);
        }
        return a;
    };

    int e = w0;
    for (; e + 2 * wpt < E; e += 3 * wpt) {
        const int u0 = __ldg(uu + e),           v0 = __ldg(vv + e);
        const int u1 = __ldg(uu + e + wpt),     v1 = __ldg(vv + e + wpt);
        const int u2 = __ldg(uu + e + 2 * wpt), v2 = __ldg(vv + e + 2 * wpt);
        uint4 pr0 = *(const uint4*)(P + (size_t)u0 * HID + lane * 8);
        uint4 qr0 = *(const uint4*)(Q + (size_t)v0 * HID + lane * 8);
        uint4 pr1 = *(const uint4*)(P + (size_t)u1 * HID + lane * 8);
        uint4 qr1 = *(const uint4*)(Q + (size_t)v1 * HID + lane * 8);
        uint4 pr2 = *(const uint4*)(P + (size_t)u2 * HID + lane * 8);
        uint4 qr2 = *(const uint4*)(Q + (size_t)v2 * HID + lane * 8);
        float a0 = dot8(pr0, qr0);
        float a1 = dot8(pr1, qr1);
        float a2 = dot8(pr2, qr2);
        #pragma unroll
        for (int off = 16; off; off >>= 1) {
            a0 += __shfl_xor_sync(0xffffffffu, a0, off);
            a1 += __shfl_xor_sync(0xffffffffu, a1, off);
            a2 += __shfl_xor_sync(0xffffffffu, a2, off);
        }
        if (lane == 0) {
            o[e] = a0 + b2v;
            o[e + wpt] = a1 + b2v;
            o[e + 2 * wpt] = a2 + b2v;
        }
    }
    for (; e < E; e += wpt) {
        const int u0 = __ldg(uu + e), v0 = __ldg(vv + e);
        uint4 pr0 = *(const uint4*)(P + (size_t)u0 * HID + lane * 8);
        uint4 qr0 = *(const uint4*)(Q + (size_t)v0 * HID + lane * 8);
        float a0 = dot8(pr0, qr0);
        #pragma unroll
        for (int off = 16; off; off >>= 1)
            a0 += __shfl_xor_sync(0xffffffffu, a0, off);
        if (lane == 0) o[e] = a0 + b2v;
    }
}

// ---------------------------------------------------------------------------
extern "C" void kernel_launch(void* const* d_in, const int* in_sizes, int n_in,
                              void* d_out, int out_size) {
    const float* user_embed = (const float*)d_in[0];
    const float* item_embed = (const float*)d_in[1];
    const int*   u_clicks   = (const int*)  d_in[2];
    const int*   v_clicks   = (const int*)  d_in[3];
    const int*   u_buys     = (const int*)  d_in[4];
    const int*   v_buys     = (const int*)  d_in[5];
    const float* W1_clicks  = (const float*)d_in[6];
    const float* b1_clicks  = (const float*)d_in[7];
    const float* W2_clicks  = (const float*)d_in[8];
    const float* b2_clicks  = (const float*)d_in[9];
    const float* W1_buys    = (const float*)d_in[10];
    const float* b1_buys    = (const float*)d_in[11];
    const float* W2_buys    = (const float*)d_in[12];
    const float* b2_buys    = (const float*)d_in[13];

    const int E = in_sizes[2];
    float* out = (float*)d_out;

    __half* tab = nullptr;
    cudaGetSymbolAddress((void**)&tab, g_tab);
    __half* Pc = tab;
    __half* Qc = Pc + P_ELEMS;
    __half* Pb = Qc + Q_ELEMS;
    __half* Qb = Pb + P_ELEMS;

    __nv_bfloat16* wext = nullptr;
    cudaGetSymbolAddress((void**)&wext, g_wext);

    static bool attr_set = false;
    if (!attr_set) {
        cudaFuncSetAttribute(gemm_kernel,
                             cudaFuncAttributeMaxDynamicSharedMemorySize, GEMM_SMEM);
        attr_set = true;
    }

    const size_t wstride = (size_t)HID * KEXT;
    convW_kernel<<<dim3(16, 4), 256>>>(W1_clicks, W1_buys, wext);

    const int gU = NTILE_U < 148 ? NTILE_U : 148;
    const int gI = NTILE_I < 148 ? NTILE_I : 148;
    gemm_kernel<<<gU, GT, GEMM_SMEM>>>(user_embed, NTILE_U, NU,
                                       wext + 0 * wstride, wext + 2 * wstride,
                                       b1_clicks, b1_buys, Pc, Pb);
    gemm_kernel<<<gI, GT, GEMM_SMEM>>>(item_embed, NTILE_I, NI,
                                       wext + 1 * wstride, wext + 3 * wstride,
                                       b1_clicks, b1_buys, Qc, Qb);

    const int eblocks = 740;                       // 5 CTAs/SM
    const int wpt = eblocks * 8 / 2;               // 2960 warps per task
    edge_kernel<<<eblocks, 256>>>(u_clicks, v_clicks, u_buys, v_buys,
                                  Pc, Qc, Pb, Qb,
                                  (const float4*)W2_clicks, b2_clicks,
                                  (const float4*)W2_buys, b2_buys,
                                  out, E, wpt);
}

// round 14
// speedup vs baseline: 1.2519x; 1.2518x over previous
#include <cuda_runtime.h>
#include <cuda_bf16.h>
#include <cuda_fp16.h>
#include <cstdint>

#define IN_DIM 128
#define HID    256
#define NU 100000
#define NI 200000
#define NTILE_U ((NU + 127) / 128)   // 782
#define NTILE_I ((NI + 127) / 128)   // 1563
#define KEXT 384                     // B: [Wh ; Wl ; Wh]

#define P_ELEMS (100000u * 256u)
#define Q_ELEMS (200000u * 256u)
__device__ __half g_tab[2u * (P_ELEMS + Q_ELEMS)];
__device__ __align__(16) __nv_bfloat16 g_wext[4][HID * KEXT];

// ---------------------------------------------------------------------------
__device__ __forceinline__ uint32_t smem_u32(const void* p) {
    uint32_t a;
    asm("{ .reg .u64 t; cvta.to.shared.u64 t, %1; cvt.u32.u64 %0, t; }"
        : "=r"(a) : "l"(p));
    return a;
}
__device__ __forceinline__ uint32_t swz(uint32_t o) { return o ^ ((o >> 3) & 0x70); }
__device__ __forceinline__ uint32_t pack2(float a, float b) {
    __nv_bfloat162 t = __floats2bfloat162_rn(a, b);
    return *(uint32_t*)&t;
}
template <int N>
__device__ __forceinline__ void cpwait() {
    asm volatile("cp.async.wait_group %0;" :: "n"(N) : "memory");
}

// ---------------------------------------------------------------------------
// convW (4 combos in one launch): W-half [128 k][256 n] -> [Wh | Wl | Wh]
// ---------------------------------------------------------------------------
__global__ __launch_bounds__(256)
void convW_kernel(const float* __restrict__ Wc, const float* __restrict__ Wb,
                  __nv_bfloat16* __restrict__ wext) {
    const int combo = blockIdx.y;
    const float* Wsrc = ((combo < 2) ? Wc : Wb) + (size_t)(combo & 1) * IN_DIM * HID;
    __nv_bfloat16* Wext = wext + (size_t)combo * HID * KEXT;
    for (int idx = blockIdx.x * 256 + threadIdx.x; idx < HID * IN_DIM;
         idx += gridDim.x * 256) {
        const int n = idx >> 7, k = idx & 127;
        const float x = Wsrc[(size_t)k * HID + n];
        const __nv_bfloat16 h = __float2bfloat16_rn(x);
        const float l = x - __bfloat162float(h);
        __nv_bfloat16* row = Wext + (size_t)n * KEXT;
        row[k]       = h;
        row[128 + k] = __float2bfloat16_rn(l);
        row[256 + k] = h;
    }
}

// ---------------------------------------------------------------------------
// persistent fused gemm (R11 core, 512 thr = 16 warps, 4m x 4n, warp 32x64).
// TRIPLE-buffered B -> single __syncthreads per chunk iteration.
// smem: Astage 64KB | Aconv 64KB | B0|B1|B2 3x32KB = 224KB.
// ---------------------------------------------------------------------------
#define KC 64
#define SM_STAGE 0
#define SM_ACONV 65536
#define SM_B_OFF (2 * 65536)
#define GEMM_SMEM (SM_B_OFF + 3 * 32768)

__device__ __forceinline__ void ldsm4(uint32_t* r, uint32_t a) {
    asm volatile("ldmatrix.sync.aligned.m8n8.x4.shared.b16 {%0,%1,%2,%3}, [%4];"
                 : "=r"(r[0]), "=r"(r[1]), "=r"(r[2]), "=r"(r[3]) : "r"(a));
}
__device__ __forceinline__ void mma16816(float* d, const uint32_t* a, const uint32_t* b) {
    asm volatile("mma.sync.aligned.m16n8k16.row.col.f32.bf16.bf16.f32 "
                 "{%0,%1,%2,%3}, {%4,%5,%6,%7}, {%8,%9}, {%0,%1,%2,%3};"
                 : "+f"(d[0]), "+f"(d[1]), "+f"(d[2]), "+f"(d[3])
                 : "r"(a[0]), "r"(a[1]), "r"(a[2]), "r"(a[3]), "r"(b[0]), "r"(b[1]));
}

__global__ __launch_bounds__(512, 1)
void gemm_kernel(const float* __restrict__ A, int ntiles, int N,
                 const __nv_bfloat16* __restrict__ W0,
                 const __nv_bfloat16* __restrict__ W1,
                 const float* __restrict__ b1_0, const float* __restrict__ b1_1,
                 __half* __restrict__ P0, __half* __restrict__ P1) {
    extern __shared__ __align__(1024) unsigned char sm[];
    const uint32_t sbase = smem_u32(sm);
    const int tid  = threadIdx.x;
    const int lane = tid & 31;
    const int wid  = tid >> 5;
    const int wm   = wid & 3;
    const int wn   = wid >> 2;

    // B chunk j (0..11) -> buffer j%3
    auto issue_b = [&](int j) {
        const char* Bb = (const char*)((j < 6) ? W0 : W1);
        const int c = j % 6;
        const uint32_t sb = sbase + SM_B_OFF + (uint32_t)(j % 3) * 32768;
        #pragma unroll
        for (int i = 0; i < 4; i++) {
            const int idx = tid + i * 512;
            const int r = idx >> 3, s = idx & 7;
            const size_t go = (size_t)r * (KEXT * 2) + c * (KC * 2) + s * 16;
            const uint32_t so = swz((uint32_t)(r * 128 + s * 16));
            asm volatile("cp.async.cg.shared.global [%0], [%1], 16;"
                         :: "r"(sb + so), "l"(Bb + go) : "memory");
        }
        asm volatile("cp.async.commit_group;" ::: "memory");
    };
    auto issue_a = [&](int t) {
        const float* Ab = A + (size_t)t * 128 * IN_DIM;
        const uint32_t sa = sbase + SM_STAGE;
        #pragma unroll
        for (int i = 0; i < 8; i++) {
            const int idx = tid + i * 512;
            const int r = idx >> 5, s = idx & 31;
            const int rg = t * 128 + r;
            const uint32_t so = (uint32_t)(r * 512 + s * 16);
            if (rg < N) {
                asm volatile("cp.async.cg.shared.global [%0], [%1], 16;"
                             :: "r"(sa + so), "l"((const char*)Ab + (size_t)r * 512 + s * 16)
                             : "memory");
            } else {
                *(uint4*)(sm + SM_STAGE + so) = make_uint4(0, 0, 0, 0);
            }
        }
        asm volatile("cp.async.commit_group;" ::: "memory");
    };
    auto convert_a = [&]() {
        #pragma unroll
        for (int i = 0; i < 8; i++) {
            const int idx = tid + i * 512;
            const int r = idx >> 5, c4 = idx & 31;
            float4 v = *(float4*)(sm + SM_STAGE + r * 512 + c4 * 16);
            float h0 = __bfloat162float(__float2bfloat16_rn(v.x));
            float h1 = __bfloat162float(__float2bfloat16_rn(v.y));
            float h2 = __bfloat162float(__float2bfloat16_rn(v.z));
            float h3 = __bfloat162float(__float2bfloat16_rn(v.w));
            uint2 uh = { pack2(h0, h1), pack2(h2, h3) };
            uint2 ul = { pack2(v.x - h0, v.y - h1), pack2(v.z - h2, v.w - h3) };
            const uint32_t ck = (uint32_t)(c4 >> 4);
            const uint32_t off = swz((uint32_t)(r * 128 + (c4 & 15) * 8));
            *(uint2*)(sm + SM_ACONV + ck * 16384 + off)         = uh;
            *(uint2*)(sm + SM_ACONV + 32768 + ck * 16384 + off) = ul;
        }
    };

    float acc[2][8][4];
    #pragma unroll
    for (int mt = 0; mt < 2; mt++)
        #pragma unroll
        for (int nt = 0; nt < 8; nt++)
            #pragma unroll
            for (int j = 0; j < 4; j++) acc[mt][nt][j] = 0.f;

    const int t0 = blockIdx.x;
    if (t0 >= ntiles) return;

    issue_a(t0);
    issue_b(0);

    const int amap[6] = {0, 1, 0, 1, 2, 3};

    for (int t = t0; t < ntiles; t += gridDim.x) {
        const int tnext = t + gridDim.x;
        const bool a_iss = (tnext < ntiles);

        cpwait<1>();          // A(t) complete; B(0) may still be in flight
        __syncthreads();
        convert_a();
        __syncthreads();

        #pragma unroll
        for (int it = 0; it < 12; it++) {
            const bool last_all = (it == 11) && !a_iss;
            if (!last_all) issue_b((it + 1) % 12);
            if (it == 0 && a_iss) issue_a(tnext);

            if (last_all)                cpwait<0>();
            else if (it < 2 && a_iss)    cpwait<2>();
            else                         cpwait<1>();
            __syncthreads();          // the ONLY barrier per iteration

            const uint32_t sa = sbase + SM_ACONV + (uint32_t)(amap[it % 6] * 16384);
            const uint32_t sb = sbase + SM_B_OFF + (uint32_t)((it % 3) * 32768);

            #pragma unroll
            for (int ks = 0; ks < KC / 16; ks++) {
                uint32_t af[2][4];
                #pragma unroll
                for (int mt = 0; mt < 2; mt++) {
                    const int row = wm * 32 + mt * 16 + (lane & 15);
                    const uint32_t off = (uint32_t)(row * 128 + ks * 32 + (lane >> 4) * 16);
                    ldsm4(af[mt], sa + swz(off));
                }
                uint32_t bfr[8][2];
                #pragma unroll
                for (int ntp = 0; ntp < 4; ntp++) {
                    const int nrow = wn * 64 + ntp * 16 + ((lane >> 4) << 3) + (lane & 7);
                    const uint32_t off = (uint32_t)(nrow * 128 + ks * 32 + ((lane >> 3) & 1) * 16);
                    uint32_t r4[4];
                    ldsm4(r4, sb + swz(off));
                    bfr[2 * ntp][0] = r4[0]; bfr[2 * ntp][1] = r4[1];
                    bfr[2 * ntp + 1][0] = r4[2]; bfr[2 * ntp + 1][1] = r4[3];
                }
                #pragma unroll
                for (int mt = 0; mt < 2; mt++)
                    #pragma unroll
                    for (int nt = 0; nt < 8; nt++)
                        mma16816(acc[mt][nt], af[mt], bfr[nt]);
            }
            // no end-of-iteration barrier: B is triple-buffered, the write of
            // buffer (it+1)%3 at iteration it is separated from its last reader
            // (MMA at it-2) by the barrier at iteration it-1.

            if (it == 5 || it == 11) {
                __half* Pt = (it == 5) ? P0 : P1;
                const float* b1 = (it == 5) ? b1_0 : b1_1;
                const int rb = t * 128 + wm * 32 + (lane >> 2);
                const int cb = wn * 64 + (lane & 3) * 2;
                #pragma unroll
                for (int mt = 0; mt < 2; mt++) {
                    #pragma unroll
                    for (int hf = 0; hf < 2; hf++) {
                        const int r = rb + mt * 16 + hf * 8;
                        if (r < N) {
                            __half* dst = Pt + (size_t)r * HID + cb;
                            #pragma unroll
                            for (int nt = 0; nt < 8; nt++) {
                                const int c = cb + nt * 8;
                                float a0 = acc[mt][nt][hf * 2]     + __ldg(b1 + c);
                                float a1 = acc[mt][nt][hf * 2 + 1] + __ldg(b1 + c + 1);
                                *(__half2*)(dst + nt * 8) = __floats2half2_rn(a0, a1);
                            }
                        }
                    }
                }
                #pragma unroll
                for (int mt = 0; mt < 2; mt++)
                    #pragma unroll
                    for (int nt = 0; nt < 8; nt++)
                        #pragma unroll
                        for (int j = 0; j < 4; j++) acc[mt][nt][j] = 0.f;
            }
        }
    }
}

// ---------------------------------------------------------------------------
// edge (R11 verbatim): persistent warps; W2/b2 in registers; 2 edges in flight.
// ---------------------------------------------------------------------------
__global__ __launch_bounds__(256)
void edge_kernel(const int* __restrict__ uc, const int* __restrict__ vc,
                 const int* __restrict__ ub, const int* __restrict__ vb,
                 const __half* __restrict__ Pc, const __half* __restrict__ Qc,
                 const __half* __restrict__ Pb, const __half* __restrict__ Qb,
                 const float4* __restrict__ W2c, const float* __restrict__ b2c,
                 const float4* __restrict__ W2b, const float* __restrict__ b2b,
                 float* __restrict__ out, int E, int wpt) {
    const int gw   = (blockIdx.x * blockDim.x + threadIdx.x) >> 5;
    const int lane = threadIdx.x & 31;
    const bool buys = (gw >= wpt);
    const int w0 = buys ? gw - wpt : gw;

    const int* uu = buys ? ub : uc;
    const int* vv = buys ? vb : vc;
    const __half* P = buys ? Pb : Pc;
    const __half* Q = buys ? Qb : Qc;
    const float4* W2 = buys ? W2b : W2c;
    float* o = out + (buys ? E : 0);

    float4 wv0 = __ldg(W2 + lane * 2);
    float4 wv1 = __ldg(W2 + lane * 2 + 1);
    const float b2v = __ldg(buys ? b2b : b2c);
    float w[8] = { wv0.x, wv0.y, wv0.z, wv0.w, wv1.x, wv1.y, wv1.z, wv1.w };

    auto dot8 = [&](const uint4& pr, const uint4& qr) -> float {
        const __half2* p2 = (const __half2*)&pr;
        const __half2* q2 = (const __half2*)&qr;
        float a = 0.f;
        #pragma unroll
        for (int i = 0; i < 4; i++) {
            float2 pf = __half22float2(p2[i]);
            float2 qf = __half22float2(q2[i]);
            a = fmaf(fmaxf(pf.x + qf.x, 0.f), w[2 * i],     a);
            a = fmaf(fmaxf(pf.y + qf.y, 0.f), w[2 * i + 1], a);
        }
        return a;
    };

    int e = w0;
    for (; e + wpt < E; e += 2 * wpt) {
        const int u0 = __ldg(uu + e),       v0 = __ldg(vv + e);
        const int u1 = __ldg(uu + e + wpt), v1 = __ldg(vv + e + wpt);
        uint4 pr0 = *(const uint4*)(P + (size_t)u0 * HID + lane * 8);
        uint4 qr0 = *(const uint4*)(Q + (size_t)v0 * HID + lane * 8);
        uint4 pr1 = *(const uint4*)(P + (size_t)u1 * HID + lane * 8);
        uint4 qr1 = *(const uint4*)(Q + (size_t)v1 * HID + lane * 8);
        float a0 = dot8(pr0, qr0);
        float a1 = dot8(pr1, qr1);
        #pragma unroll
        for (int off = 16; off; off >>= 1) {
            a0 += __shfl_xor_sync(0xffffffffu, a0, off);
            a1 += __shfl_xor_sync(0xffffffffu, a1, off);
        }
        if (lane == 0) { o[e] = a0 + b2v; o[e + wpt] = a1 + b2v; }
    }
    if (e < E) {
        const int u0 = __ldg(uu + e), v0 = __ldg(vv + e);
        uint4 pr0 = *(const uint4*)(P + (size_t)u0 * HID + lane * 8);
        uint4 qr0 = *(const uint4*)(Q + (size_t)v0 * HID + lane * 8);
        float a0 = dot8(pr0, qr0);
        #pragma unroll
        for (int off = 16; off; off >>= 1)
            a0 += __shfl_xor_sync(0xffffffffu, a0, off);
        if (lane == 0) o[e] = a0 + b2v;
    }
}

// ---------------------------------------------------------------------------
extern "C" void kernel_launch(void* const* d_in, const int* in_sizes, int n_in,
                              void* d_out, int out_size) {
    const float* user_embed = (const float*)d_in[0];
    const float* item_embed = (const float*)d_in[1];
    const int*   u_clicks   = (const int*)  d_in[2];
    const int*   v_clicks   = (const int*)  d_in[3];
    const int*   u_buys     = (const int*)  d_in[4];
    const int*   v_buys     = (const int*)  d_in[5];
    const float* W1_clicks  = (const float*)d_in[6];
    const float* b1_clicks  = (const float*)d_in[7];
    const float* W2_clicks  = (const float*)d_in[8];
    const float* b2_clicks  = (const float*)d_in[9];
    const float* W1_buys    = (const float*)d_in[10];
    const float* b1_buys    = (const float*)d_in[11];
    const float* W2_buys    = (const float*)d_in[12];
    const float* b2_buys    = (const float*)d_in[13];

    const int E = in_sizes[2];
    float* out = (float*)d_out;

    __half* tab = nullptr;
    cudaGetSymbolAddress((void**)&tab, g_tab);
    __half* Pc = tab;
    __half* Qc = Pc + P_ELEMS;
    __half* Pb = Qc + Q_ELEMS;
    __half* Qb = Pb + P_ELEMS;

    __nv_bfloat16* wext = nullptr;
    cudaGetSymbolAddress((void**)&wext, g_wext);

    static bool attr_set = false;
    if (!attr_set) {
        cudaFuncSetAttribute(gemm_kernel,
                             cudaFuncAttributeMaxDynamicSharedMemorySize, GEMM_SMEM);
        attr_set = true;
    }

    const size_t wstride = (size_t)HID * KEXT;
    convW_kernel<<<dim3(16, 4), 256>>>(W1_clicks, W1_buys, wext);

    const int gU = NTILE_U < 148 ? NTILE_U : 148;
    const int gI = NTILE_I < 148 ? NTILE_I : 148;
    gemm_kernel<<<gU, 512, GEMM_SMEM>>>(user_embed, NTILE_U, NU,
                                        wext + 0 * wstride, wext + 2 * wstride,
                                        b1_clicks, b1_buys, Pc, Pb);
    gemm_kernel<<<gI, 512, GEMM_SMEM>>>(item_embed, NTILE_I, NI,
                                        wext + 1 * wstride, wext + 3 * wstride,
                                        b1_clicks, b1_buys, Qc, Qb);

    const int eblocks = 740;                       // 5 CTAs/SM
    const int wpt = eblocks * 8 / 2;               // 2960 warps per task
    edge_kernel<<<eblocks, 256>>>(u_clicks, v_clicks, u_buys, v_buys,
                                  Pc, Qc, Pb, Qb,
                                  (const float4*)W2_clicks, b2_clicks,
                                  (const float4*)W2_buys, b2_buys,
                                  out, E, wpt);
}

// round 15
// speedup vs baseline: 1.4604x; 1.1665x over previous
#include <cuda_runtime.h>
#include <cuda_bf16.h>
#include <cuda_fp16.h>
#include <cstdint>

#define IN_DIM 128
#define HID    256
#define NU 100000
#define NI 200000
#define NTILE_U ((NU + 127) / 128)   // 782
#define NTILE_I ((NI + 127) / 128)   // 1563

#define P_ELEMS (100000u * 256u)
#define Q_ELEMS (200000u * 256u)
__device__ __half g_tab[2u * (P_ELEMS + Q_ELEMS)];
__device__ __align__(16) __half g_wext[4][HID * IN_DIM];   // fp16 W, [n][k]

// ---------------------------------------------------------------------------
__device__ __forceinline__ uint32_t smem_u32(const void* p) {
    uint32_t a;
    asm("{ .reg .u64 t; cvta.to.shared.u64 t, %1; cvt.u32.u64 %0, t; }"
        : "=r"(a) : "l"(p));
    return a;
}
__device__ __forceinline__ uint32_t swz(uint32_t o) { return o ^ ((o >> 3) & 0x70); }
__device__ __forceinline__ uint32_t packh2(float a, float b) {
    __half2 t = __floats2half2_rn(a, b);
    return *(uint32_t*)&t;
}
template <int N>
__device__ __forceinline__ void cpwait() {
    asm volatile("cp.async.wait_group %0;" :: "n"(N) : "memory");
}

// ---------------------------------------------------------------------------
// convW: 4 combos in one launch; W-half [128 k][256 n] fp32 -> fp16 [n][k]
// ---------------------------------------------------------------------------
__global__ __launch_bounds__(256)
void convW_kernel(const float* __restrict__ Wc, const float* __restrict__ Wb,
                  __half* __restrict__ wext) {
    const int combo = blockIdx.y;
    const float* Wsrc = ((combo < 2) ? Wc : Wb) + (size_t)(combo & 1) * IN_DIM * HID;
    __half* Wext = wext + (size_t)combo * HID * IN_DIM;
    for (int idx = blockIdx.x * 256 + threadIdx.x; idx < HID * IN_DIM;
         idx += gridDim.x * 256) {
        const int n = idx >> 7, k = idx & 127;
        Wext[(size_t)n * IN_DIM + k] = __float2half_rn(Wsrc[(size_t)k * HID + n]);
    }
}

// ---------------------------------------------------------------------------
// persistent fused gemm: fp16 two-pass split. A -> [Ah0|Ah1|Al0|Al1] fp16
// (4 chunks of 16KB, swizzled). Per tile: 8 chunk-iterations =
// 2 tasks x { (Ah0,W0),(Ah1,W1),(Al0,W0),(Al1,W1) }. B (W chunk, 32KB)
// triple-buffered with a GLOBAL mod-3 cursor (8%3!=0 so it must not reset
// per tile). Single __syncthreads per iteration (R14 invariant).
// smem: Astage 64KB | Aconv 64KB | B0|B1|B2 3x32KB = 224KB.
// ---------------------------------------------------------------------------
#define KC 64
#define SM_STAGE 0
#define SM_ACONV 65536
#define SM_B_OFF (2 * 65536)
#define GEMM_SMEM (SM_B_OFF + 3 * 32768)

__device__ __forceinline__ void ldsm4(uint32_t* r, uint32_t a) {
    asm volatile("ldmatrix.sync.aligned.m8n8.x4.shared.b16 {%0,%1,%2,%3}, [%4];"
                 : "=r"(r[0]), "=r"(r[1]), "=r"(r[2]), "=r"(r[3]) : "r"(a));
}
__device__ __forceinline__ void mma16816(float* d, const uint32_t* a, const uint32_t* b) {
    asm volatile("mma.sync.aligned.m16n8k16.row.col.f32.f16.f16.f32 "
                 "{%0,%1,%2,%3}, {%4,%5,%6,%7}, {%8,%9}, {%0,%1,%2,%3};"
                 : "+f"(d[0]), "+f"(d[1]), "+f"(d[2]), "+f"(d[3])
                 : "r"(a[0]), "r"(a[1]), "r"(a[2]), "r"(a[3]), "r"(b[0]), "r"(b[1]));
}

__global__ __launch_bounds__(512, 1)
void gemm_kernel(const float* __restrict__ A, int ntiles, int N,
                 const __half* __restrict__ W0,
                 const __half* __restrict__ W1,
                 const float* __restrict__ b1_0, const float* __restrict__ b1_1,
                 __half* __restrict__ P0, __half* __restrict__ P1) {
    extern __shared__ __align__(1024) unsigned char sm[];
    const uint32_t sbase = smem_u32(sm);
    const int tid  = threadIdx.x;
    const int lane = tid & 31;
    const int wid  = tid >> 5;
    const int wm   = wid & 3;
    const int wn   = wid >> 2;

    // chunk index cc in 0..7: task = cc>>2, W k-chunk = cc&1. buf: explicit.
    auto issue_b = [&](int cc, int buf) {
        const char* Bb = (const char*)((cc < 4) ? W0 : W1);
        const int c = cc & 1;
        const uint32_t sb = sbase + SM_B_OFF + (uint32_t)buf * 32768;
        #pragma unroll
        for (int i = 0; i < 4; i++) {
            const int idx = tid + i * 512;
            const int r = idx >> 3, s = idx & 7;
            const size_t go = (size_t)r * (IN_DIM * 2) + c * (KC * 2) + s * 16;
            const uint32_t so = swz((uint32_t)(r * 128 + s * 16));
            asm volatile("cp.async.cg.shared.global [%0], [%1], 16;"
                         :: "r"(sb + so), "l"(Bb + go) : "memory");
        }
        asm volatile("cp.async.commit_group;" ::: "memory");
    };
    auto issue_a = [&](int t) {
        const float* Ab = A + (size_t)t * 128 * IN_DIM;
        const uint32_t sa = sbase + SM_STAGE;
        #pragma unroll
        for (int i = 0; i < 8; i++) {
            const int idx = tid + i * 512;
            const int r = idx >> 5, s = idx & 31;
            const int rg = t * 128 + r;
            const uint32_t so = (uint32_t)(r * 512 + s * 16);
            if (rg < N) {
                asm volatile("cp.async.cg.shared.global [%0], [%1], 16;"
                             :: "r"(sa + so), "l"((const char*)Ab + (size_t)r * 512 + s * 16)
                             : "memory");
            } else {
                *(uint4*)(sm + SM_STAGE + so) = make_uint4(0, 0, 0, 0);
            }
        }
        asm volatile("cp.async.commit_group;" ::: "memory");
    };
    // fp32 -> fp16 split: Ah (chunks 0,1), Al = A - Ah (chunks 2,3)
    auto convert_a = [&]() {
        #pragma unroll
        for (int i = 0; i < 8; i++) {
            const int idx = tid + i * 512;
            const int r = idx >> 5, c4 = idx & 31;
            float4 v = *(float4*)(sm + SM_STAGE + r * 512 + c4 * 16);
            __half hx = __float2half_rn(v.x), hy = __float2half_rn(v.y);
            __half hz = __float2half_rn(v.z), hw = __float2half_rn(v.w);
            float fx = __half2float(hx), fy = __half2float(hy);
            float fz = __half2float(hz), fw = __half2float(hw);
            __half2 h01; h01.x = hx; h01.y = hy;
            __half2 h23; h23.x = hz; h23.y = hw;
            uint2 uh = { *(uint32_t*)&h01, *(uint32_t*)&h23 };
            uint2 ul = { packh2(v.x - fx, v.y - fy), packh2(v.z - fz, v.w - fw) };
            const uint32_t ck = (uint32_t)(c4 >> 4);
            const uint32_t off = swz((uint32_t)(r * 128 + (c4 & 15) * 8));
            *(uint2*)(sm + SM_ACONV + ck * 16384 + off)         = uh;   // Ah
            *(uint2*)(sm + SM_ACONV + 32768 + ck * 16384 + off) = ul;   // Al
        }
    };

    float acc[2][8][4];
    #pragma unroll
    for (int mt = 0; mt < 2; mt++)
        #pragma unroll
        for (int nt = 0; nt < 8; nt++)
            #pragma unroll
            for (int j = 0; j < 4; j++) acc[mt][nt][j] = 0.f;

    const int t0 = blockIdx.x;
    if (t0 >= ntiles) return;

    issue_a(t0);
    issue_b(0, 0);
    int bcur = 0;   // global mod-3 B-buffer cursor (carried across tiles)

    // Aconv chunk per iteration c: Ah0,Ah1,Al0,Al1 repeated for task 1
    const int amap[8] = {0, 1, 2, 3, 0, 1, 2, 3};

    for (int t = t0; t < ntiles; t += gridDim.x) {
        const int tnext = t + gridDim.x;
        const bool a_iss = (tnext < ntiles);

        cpwait<1>();          // A(t) complete; B(chunk 0) may still be in flight
        __syncthreads();
        convert_a();
        __syncthreads();

        #pragma unroll
        for (int c = 0; c < 8; c++) {
            const bool last_all = (c == 7) && !a_iss;
            if (!last_all) issue_b((c + 1) & 7, (bcur + 1 == 3) ? 0 : bcur + 1);
            if (c == 0 && a_iss) issue_a(tnext);

            if (last_all)              cpwait<0>();
            else if (c < 2 && a_iss)   cpwait<2>();
            else                       cpwait<1>();
            __syncthreads();          // the only barrier per iteration

            const uint32_t sa = sbase + SM_ACONV + (uint32_t)(amap[c] * 16384);
            const uint32_t sb = sbase + SM_B_OFF + (uint32_t)(bcur * 32768);

            #pragma unroll
            for (int ks = 0; ks < KC / 16; ks++) {
                uint32_t af[2][4];
                #pragma unroll
                for (int mt = 0; mt < 2; mt++) {
                    const int row = wm * 32 + mt * 16 + (lane & 15);
                    const uint32_t off = (uint32_t)(row * 128 + ks * 32 + (lane >> 4) * 16);
                    ldsm4(af[mt], sa + swz(off));
                }
                uint32_t bfr[8][2];
                #pragma unroll
                for (int ntp = 0; ntp < 4; ntp++) {
                    const int nrow = wn * 64 + ntp * 16 + ((lane >> 4) << 3) + (lane & 7);
                    const uint32_t off = (uint32_t)(nrow * 128 + ks * 32 + ((lane >> 3) & 1) * 16);
                    uint32_t r4[4];
                    ldsm4(r4, sb + swz(off));
                    bfr[2 * ntp][0] = r4[0]; bfr[2 * ntp][1] = r4[1];
                    bfr[2 * ntp + 1][0] = r4[2]; bfr[2 * ntp + 1][1] = r4[3];
                }
                #pragma unroll
                for (int mt = 0; mt < 2; mt++)
                    #pragma unroll
                    for (int nt = 0; nt < 8; nt++)
                        mma16816(acc[mt][nt], af[mt], bfr[nt]);
            }
            // no trailing barrier: triple-buffered B, writer of buffer n+1 is
            // separated from its last reader (n-2) by the barrier at n-1.

            if (c == 3 || c == 7) {
                __half* Pt = (c == 3) ? P0 : P1;
                const float* b1 = (c == 3) ? b1_0 : b1_1;
                const int rb = t * 128 + wm * 32 + (lane >> 2);
                const int cb = wn * 64 + (lane & 3) * 2;
                #pragma unroll
                for (int mt = 0; mt < 2; mt++) {
                    #pragma unroll
                    for (int hf = 0; hf < 2; hf++) {
                        const int r = rb + mt * 16 + hf * 8;
                        if (r < N) {
                            __half* dst = Pt + (size_t)r * HID + cb;
                            #pragma unroll
                            for (int nt = 0; nt < 8; nt++) {
                                const int cc2 = cb + nt * 8;
                                float a0 = acc[mt][nt][hf * 2]     + __ldg(b1 + cc2);
                                float a1 = acc[mt][nt][hf * 2 + 1] + __ldg(b1 + cc2 + 1);
                                *(__half2*)(dst + nt * 8) = __floats2half2_rn(a0, a1);
                            }
                        }
                    }
                }
                #pragma unroll
                for (int mt = 0; mt < 2; mt++)
                    #pragma unroll
                    for (int nt = 0; nt < 8; nt++)
                        #pragma unroll
                        for (int j = 0; j < 4; j++) acc[mt][nt][j] = 0.f;
            }
            bcur = (bcur + 1 == 3) ? 0 : bcur + 1;
        }
    }
}

// ---------------------------------------------------------------------------
// edge (unchanged): persistent warps; W2/b2 in registers; 2 edges in flight.
// ---------------------------------------------------------------------------
__global__ __launch_bounds__(256)
void edge_kernel(const int* __restrict__ uc, const int* __restrict__ vc,
                 const int* __restrict__ ub, const int* __restrict__ vb,
                 const __half* __restrict__ Pc, const __half* __restrict__ Qc,
                 const __half* __restrict__ Pb, const __half* __restrict__ Qb,
                 const float4* __restrict__ W2c, const float* __restrict__ b2c,
                 const float4* __restrict__ W2b, const float* __restrict__ b2b,
                 float* __restrict__ out, int E, int wpt) {
    const int gw   = (blockIdx.x * blockDim.x + threadIdx.x) >> 5;
    const int lane = threadIdx.x & 31;
    const bool buys = (gw >= wpt);
    const int w0 = buys ? gw - wpt : gw;

    const int* uu = buys ? ub : uc;
    const int* vv = buys ? vb : vc;
    const __half* P = buys ? Pb : Pc;
    const __half* Q = buys ? Qb : Qc;
    const float4* W2 = buys ? W2b : W2c;
    float* o = out + (buys ? E : 0);

    float4 wv0 = __ldg(W2 + lane * 2);
    float4 wv1 = __ldg(W2 + lane * 2 + 1);
    const float b2v = __ldg(buys ? b2b : b2c);
    float w[8] = { wv0.x, wv0.y, wv0.z, wv0.w, wv1.x, wv1.y, wv1.z, wv1.w };

    auto dot8 = [&](const uint4& pr, const uint4& qr) -> float {
        const __half2* p2 = (const __half2*)&pr;
        const __half2* q2 = (const __half2*)&qr;
        float a = 0.f;
        #pragma unroll
        for (int i = 0; i < 4; i++) {
            float2 pf = __half22float2(p2[i]);
            float2 qf = __half22float2(q2[i]);
            a = fmaf(fmaxf(pf.x + qf.x, 0.f), w[2 * i],     a);
            a = fmaf(fmaxf(pf.y + qf.y, 0.f), w[2 * i + 1], a);
        }
        return a;
    };

    int e = w0;
    for (; e + wpt < E; e += 2 * wpt) {
        const int u0 = __ldg(uu + e),       v0 = __ldg(vv + e);
        const int u1 = __ldg(uu + e + wpt), v1 = __ldg(vv + e + wpt);
        uint4 pr0 = *(const uint4*)(P + (size_t)u0 * HID + lane * 8);
        uint4 qr0 = *(const uint4*)(Q + (size_t)v0 * HID + lane * 8);
        uint4 pr1 = *(const uint4*)(P + (size_t)u1 * HID + lane * 8);
        uint4 qr1 = *(const uint4*)(Q + (size_t)v1 * HID + lane * 8);
        float a0 = dot8(pr0, qr0);
        float a1 = dot8(pr1, qr1);
        #pragma unroll
        for (int off = 16; off; off >>= 1) {
            a0 += __shfl_xor_sync(0xffffffffu, a0, off);
            a1 += __shfl_xor_sync(0xffffffffu, a1, off);
        }
        if (lane == 0) { o[e] = a0 + b2v; o[e + wpt] = a1 + b2v; }
    }
    if (e < E) {
        const int u0 = __ldg(uu + e), v0 = __ldg(vv + e);
        uint4 pr0 = *(const uint4*)(P + (size_t)u0 * HID + lane * 8);
        uint4 qr0 = *(const uint4*)(Q + (size_t)v0 * HID + lane * 8);
        float a0 = dot8(pr0, qr0);
        #pragma unroll
        for (int off = 16; off; off >>= 1)
            a0 += __shfl_xor_sync(0xffffffffu, a0, off);
        if (lane == 0) o[e] = a0 + b2v;
    }
}

// ---------------------------------------------------------------------------
extern "C" void kernel_launch(void* const* d_in, const int* in_sizes, int n_in,
                              void* d_out, int out_size) {
    const float* user_embed = (const float*)d_in[0];
    const float* item_embed = (const float*)d_in[1];
    const int*   u_clicks   = (const int*)  d_in[2];
    const int*   v_clicks   = (const int*)  d_in[3];
    const int*   u_buys     = (const int*)  d_in[4];
    const int*   v_buys     = (const int*)  d_in[5];
    const float* W1_clicks  = (const float*)d_in[6];
    const float* b1_clicks  = (const float*)d_in[7];
    const float* W2_clicks  = (const float*)d_in[8];
    const float* b2_clicks  = (const float*)d_in[9];
    const float* W1_buys    = (const float*)d_in[10];
    const float* b1_buys    = (const float*)d_in[11];
    const float* W2_buys    = (const float*)d_in[12];
    const float* b2_buys    = (const float*)d_in[13];

    const int E = in_sizes[2];
    float* out = (float*)d_out;

    __half* tab = nullptr;
    cudaGetSymbolAddress((void**)&tab, g_tab);
    __half* Pc = tab;
    __half* Qc = Pc + P_ELEMS;
    __half* Pb = Qc + Q_ELEMS;
    __half* Qb = Pb + P_ELEMS;

    __half* wext = nullptr;
    cudaGetSymbolAddress((void**)&wext, g_wext);

    static bool attr_set = false;
    if (!attr_set) {
        cudaFuncSetAttribute(gemm_kernel,
                             cudaFuncAttributeMaxDynamicSharedMemorySize, GEMM_SMEM);
        attr_set = true;
    }

    const size_t wstride = (size_t)HID * IN_DIM;
    convW_kernel<<<dim3(16, 4), 256>>>(W1_clicks, W1_buys, wext);

    const int gU = NTILE_U < 148 ? NTILE_U : 148;
    const int gI = NTILE_I < 148 ? NTILE_I : 148;
    gemm_kernel<<<gU, 512, GEMM_SMEM>>>(user_embed, NTILE_U, NU,
                                        wext + 0 * wstride, wext + 2 * wstride,
                                        b1_clicks, b1_buys, Pc, Pb);
    gemm_kernel<<<gI, 512, GEMM_SMEM>>>(item_embed, NTILE_I, NI,
                                        wext + 1 * wstride, wext + 3 * wstride,
                                        b1_clicks, b1_buys, Qc, Qb);

    const int eblocks = 740;                       // 5 CTAs/SM
    const int wpt = eblocks * 8 / 2;               // 2960 warps per task
    edge_kernel<<<eblocks, 256>>>(u_clicks, v_clicks, u_buys, v_buys,
                                  Pc, Qc, Pb, Qb,
                                  (const float4*)W2_clicks, b2_clicks,
                                  (const float4*)W2_buys, b2_buys,
                                  out, E, wpt);
}

// round 16
// speedup vs baseline: 1.7456x; 1.1953x over previous
#include <cuda_runtime.h>
#include <cuda_bf16.h>
#include <cuda_fp16.h>
#include <cstdint>

#define IN_DIM 128
#define HID    256
#define NU 100000
#define NI 200000
#define NTILE_U ((NU + 127) / 128)   // 782
#define NTILE_I ((NI + 127) / 128)   // 1563

#define P_ELEMS (100000u * 256u)
#define Q_ELEMS (200000u * 256u)
__device__ __half g_tab[2u * (P_ELEMS + Q_ELEMS)];
__device__ __align__(16) __half g_wext[4][HID * IN_DIM];   // fp16 W, [n][k]

// ---------------------------------------------------------------------------
__device__ __forceinline__ uint32_t smem_u32(const void* p) {
    uint32_t a;
    asm("{ .reg .u64 t; cvta.to.shared.u64 t, %1; cvt.u32.u64 %0, t; }"
        : "=r"(a) : "l"(p));
    return a;
}
__device__ __forceinline__ uint32_t swz(uint32_t o) { return o ^ ((o >> 3) & 0x70); }
template <int N>
__device__ __forceinline__ void cpwait() {
    asm volatile("cp.async.wait_group %0;" :: "n"(N) : "memory");
}

// ---------------------------------------------------------------------------
// convW: 4 combos in one launch; W-half [128 k][256 n] fp32 -> fp16 [n][k]
// ---------------------------------------------------------------------------
__global__ __launch_bounds__(256)
void convW_kernel(const float* __restrict__ Wc, const float* __restrict__ Wb,
                  __half* __restrict__ wext) {
    const int combo = blockIdx.y;
    const float* Wsrc = ((combo < 2) ? Wc : Wb) + (size_t)(combo & 1) * IN_DIM * HID;
    __half* Wext = wext + (size_t)combo * HID * IN_DIM;
    for (int idx = blockIdx.x * 256 + threadIdx.x; idx < HID * IN_DIM;
         idx += gridDim.x * 256) {
        const int n = idx >> 7, k = idx & 127;
        Wext[(size_t)n * IN_DIM + k] = __float2half_rn(Wsrc[(size_t)k * HID + n]);
    }
}

// ---------------------------------------------------------------------------
// persistent fused gemm: SINGLE-pass fp16. A -> [Ah0|Ah1] fp16 (2 chunks of
// 16KB, swizzled). Per tile: 4 chunk-iterations = 2 tasks x 2 W-chunks.
// B (32KB) triple-buffered with a GLOBAL mod-3 cursor (4%3!=0, rotation
// carried across tiles). Single __syncthreads per iteration.
// smem: Astage fp32 64KB | Aconv fp16 32KB | B0|B1|B2 3x32KB = 192KB.
// ---------------------------------------------------------------------------
#define KC 64
#define SM_STAGE 0
#define SM_ACONV 65536
#define SM_B_OFF (65536 + 32768)
#define GEMM_SMEM (SM_B_OFF + 3 * 32768)

__device__ __forceinline__ void ldsm4(uint32_t* r, uint32_t a) {
    asm volatile("ldmatrix.sync.aligned.m8n8.x4.shared.b16 {%0,%1,%2,%3}, [%4];"
                 : "=r"(r[0]), "=r"(r[1]), "=r"(r[2]), "=r"(r[3]) : "r"(a));
}
__device__ __forceinline__ void mma16816(float* d, const uint32_t* a, const uint32_t* b) {
    asm volatile("mma.sync.aligned.m16n8k16.row.col.f32.f16.f16.f32 "
                 "{%0,%1,%2,%3}, {%4,%5,%6,%7}, {%8,%9}, {%0,%1,%2,%3};"
                 : "+f"(d[0]), "+f"(d[1]), "+f"(d[2]), "+f"(d[3])
                 : "r"(a[0]), "r"(a[1]), "r"(a[2]), "r"(a[3]), "r"(b[0]), "r"(b[1]));
}

__global__ __launch_bounds__(512, 1)
void gemm_kernel(const float* __restrict__ A, int ntiles, int N,
                 const __half* __restrict__ W0,
                 const __half* __restrict__ W1,
                 const float* __restrict__ b1_0, const float* __restrict__ b1_1,
                 __half* __restrict__ P0, __half* __restrict__ P1) {
    extern __shared__ __align__(1024) unsigned char sm[];
    const uint32_t sbase = smem_u32(sm);
    const int tid  = threadIdx.x;
    const int lane = tid & 31;
    const int wid  = tid >> 5;
    const int wm   = wid & 3;
    const int wn   = wid >> 2;

    // chunk index cc in 0..3: task = cc>>1, W k-chunk = cc&1.
    auto issue_b = [&](int cc, int buf) {
        const char* Bb = (const char*)((cc < 2) ? W0 : W1);
        const int c = cc & 1;
        const uint32_t sb = sbase + SM_B_OFF + (uint32_t)buf * 32768;
        #pragma unroll
        for (int i = 0; i < 4; i++) {
            const int idx = tid + i * 512;
            const int r = idx >> 3, s = idx & 7;
            const size_t go = (size_t)r * (IN_DIM * 2) + c * (KC * 2) + s * 16;
            const uint32_t so = swz((uint32_t)(r * 128 + s * 16));
            asm volatile("cp.async.cg.shared.global [%0], [%1], 16;"
                         :: "r"(sb + so), "l"(Bb + go) : "memory");
        }
        asm volatile("cp.async.commit_group;" ::: "memory");
    };
    auto issue_a = [&](int t) {
        const float* Ab = A + (size_t)t * 128 * IN_DIM;
        const uint32_t sa = sbase + SM_STAGE;
        #pragma unroll
        for (int i = 0; i < 8; i++) {
            const int idx = tid + i * 512;
            const int r = idx >> 5, s = idx & 31;
            const int rg = t * 128 + r;
            const uint32_t so = (uint32_t)(r * 512 + s * 16);
            if (rg < N) {
                asm volatile("cp.async.cg.shared.global [%0], [%1], 16;"
                             :: "r"(sa + so), "l"((const char*)Ab + (size_t)r * 512 + s * 16)
                             : "memory");
            } else {
                *(uint4*)(sm + SM_STAGE + so) = make_uint4(0, 0, 0, 0);
            }
        }
        asm volatile("cp.async.commit_group;" ::: "memory");
    };
    // fp32 -> fp16 (no residual): chunks 0,1 of Aconv
    auto convert_a = [&]() {
        #pragma unroll
        for (int i = 0; i < 8; i++) {
            const int idx = tid + i * 512;
            const int r = idx >> 5, c4 = idx & 31;
            float4 v = *(float4*)(sm + SM_STAGE + r * 512 + c4 * 16);
            __half2 h01 = __floats2half2_rn(v.x, v.y);
            __half2 h23 = __floats2half2_rn(v.z, v.w);
            uint2 uh = { *(uint32_t*)&h01, *(uint32_t*)&h23 };
            const uint32_t ck = (uint32_t)(c4 >> 4);
            const uint32_t off = swz((uint32_t)(r * 128 + (c4 & 15) * 8));
            *(uint2*)(sm + SM_ACONV + ck * 16384 + off) = uh;
        }
    };

    float acc[2][8][4];
    #pragma unroll
    for (int mt = 0; mt < 2; mt++)
        #pragma unroll
        for (int nt = 0; nt < 8; nt++)
            #pragma unroll
            for (int j = 0; j < 4; j++) acc[mt][nt][j] = 0.f;

    const int t0 = blockIdx.x;
    if (t0 >= ntiles) return;

    issue_a(t0);
    issue_b(0, 0);
    int bcur = 0;   // global mod-3 B-buffer cursor (carried across tiles)

    // Aconv chunk per iteration c (0..3): W chunk parity selects A chunk
    const int amap[4] = {0, 1, 0, 1};

    for (int t = t0; t < ntiles; t += gridDim.x) {
        const int tnext = t + gridDim.x;
        const bool a_iss = (tnext < ntiles);

        cpwait<1>();          // A(t) complete; B(chunk 0) may still be in flight
        __syncthreads();
        convert_a();
        __syncthreads();

        #pragma unroll
        for (int c = 0; c < 4; c++) {
            const bool last_all = (c == 3) && !a_iss;
            if (!last_all) issue_b((c + 1) & 3, (bcur + 1 == 3) ? 0 : bcur + 1);
            if (c == 0 && a_iss) issue_a(tnext);

            if (last_all)              cpwait<0>();
            else if (c < 2 && a_iss)   cpwait<2>();
            else                       cpwait<1>();
            __syncthreads();          // the only barrier per iteration

            const uint32_t sa = sbase + SM_ACONV + (uint32_t)(amap[c] * 16384);
            const uint32_t sb = sbase + SM_B_OFF + (uint32_t)(bcur * 32768);

            #pragma unroll
            for (int ks = 0; ks < KC / 16; ks++) {
                uint32_t af[2][4];
                #pragma unroll
                for (int mt = 0; mt < 2; mt++) {
                    const int row = wm * 32 + mt * 16 + (lane & 15);
                    const uint32_t off = (uint32_t)(row * 128 + ks * 32 + (lane >> 4) * 16);
                    ldsm4(af[mt], sa + swz(off));
                }
                uint32_t bfr[8][2];
                #pragma unroll
                for (int ntp = 0; ntp < 4; ntp++) {
                    const int nrow = wn * 64 + ntp * 16 + ((lane >> 4) << 3) + (lane & 7);
                    const uint32_t off = (uint32_t)(nrow * 128 + ks * 32 + ((lane >> 3) & 1) * 16);
                    uint32_t r4[4];
                    ldsm4(r4, sb + swz(off));
                    bfr[2 * ntp][0] = r4[0]; bfr[2 * ntp][1] = r4[1];
                    bfr[2 * ntp + 1][0] = r4[2]; bfr[2 * ntp + 1][1] = r4[3];
                }
                #pragma unroll
                for (int mt = 0; mt < 2; mt++)
                    #pragma unroll
                    for (int nt = 0; nt < 8; nt++)
                        mma16816(acc[mt][nt], af[mt], bfr[nt]);
            }
            // no trailing barrier: triple-buffered B (writer of buffer n+1
            // separated from last reader n-2 by the barrier at n-1).

            if (c == 1 || c == 3) {
                __half* Pt = (c == 1) ? P0 : P1;
                const float* b1 = (c == 1) ? b1_0 : b1_1;
                const int rb = t * 128 + wm * 32 + (lane >> 2);
                const int cb = wn * 64 + (lane & 3) * 2;
                #pragma unroll
                for (int mt = 0; mt < 2; mt++) {
                    #pragma unroll
                    for (int hf = 0; hf < 2; hf++) {
                        const int r = rb + mt * 16 + hf * 8;
                        if (r < N) {
                            __half* dst = Pt + (size_t)r * HID + cb;
                            #pragma unroll
                            for (int nt = 0; nt < 8; nt++) {
                                const int cc2 = cb + nt * 8;
                                float a0 = acc[mt][nt][hf * 2]     + __ldg(b1 + cc2);
                                float a1 = acc[mt][nt][hf * 2 + 1] + __ldg(b1 + cc2 + 1);
                                *(__half2*)(dst + nt * 8) = __floats2half2_rn(a0, a1);
                            }
                        }
                    }
                }
                #pragma unroll
                for (int mt = 0; mt < 2; mt++)
                    #pragma unroll
                    for (int nt = 0; nt < 8; nt++)
                        #pragma unroll
                        for (int j = 0; j < 4; j++) acc[mt][nt][j] = 0.f;
            }
            bcur = (bcur + 1 == 3) ? 0 : bcur + 1;
        }
    }
}

// ---------------------------------------------------------------------------
// edge (unchanged): persistent warps; W2/b2 in registers; 2 edges in flight.
// ---------------------------------------------------------------------------
__global__ __launch_bounds__(256)
void edge_kernel(const int* __restrict__ uc, const int* __restrict__ vc,
                 const int* __restrict__ ub, const int* __restrict__ vb,
                 const __half* __restrict__ Pc, const __half* __restrict__ Qc,
                 const __half* __restrict__ Pb, const __half* __restrict__ Qb,
                 const float4* __restrict__ W2c, const float* __restrict__ b2c,
                 const float4* __restrict__ W2b, const float* __restrict__ b2b,
                 float* __restrict__ out, int E, int wpt) {
    const int gw   = (blockIdx.x * blockDim.x + threadIdx.x) >> 5;
    const int lane = threadIdx.x & 31;
    const bool buys = (gw >= wpt);
    const int w0 = buys ? gw - wpt : gw;

    const int* uu = buys ? ub : uc;
    const int* vv = buys ? vb : vc;
    const __half* P = buys ? Pb : Pc;
    const __half* Q = buys ? Qb : Qc;
    const float4* W2 = buys ? W2b : W2c;
    float* o = out + (buys ? E : 0);

    float4 wv0 = __ldg(W2 + lane * 2);
    float4 wv1 = __ldg(W2 + lane * 2 + 1);
    const float b2v = __ldg(buys ? b2b : b2c);
    float w[8] = { wv0.x, wv0.y, wv0.z, wv0.w, wv1.x, wv1.y, wv1.z, wv1.w };

    auto dot8 = [&](const uint4& pr, const uint4& qr) -> float {
        const __half2* p2 = (const __half2*)&pr;
        const __half2* q2 = (const __half2*)&qr;
        float a = 0.f;
        #pragma unroll
        for (int i = 0; i < 4; i++) {
            float2 pf = __half22float2(p2[i]);
            float2 qf = __half22float2(q2[i]);
            a = fmaf(fmaxf(pf.x + qf.x, 0.f), w[2 * i],     a);
            a = fmaf(fmaxf(pf.y + qf.y, 0.f), w[2 * i + 1], a);
        }
        return a;
    };

    int e = w0;
    for (; e + wpt < E; e += 2 * wpt) {
        const int u0 = __ldg(uu + e),       v0 = __ldg(vv + e);
        const int u1 = __ldg(uu + e + wpt), v1 = __ldg(vv + e + wpt);
        uint4 pr0 = *(const uint4*)(P + (size_t)u0 * HID + lane * 8);
        uint4 qr0 = *(const uint4*)(Q + (size_t)v0 * HID + lane * 8);
        uint4 pr1 = *(const uint4*)(P + (size_t)u1 * HID + lane * 8);
        uint4 qr1 = *(const uint4*)(Q + (size_t)v1 * HID + lane * 8);
        float a0 = dot8(pr0, qr0);
        float a1 = dot8(pr1, qr1);
        #pragma unroll
        for (int off = 16; off; off >>= 1) {
            a0 += __shfl_xor_sync(0xffffffffu, a0, off);
            a1 += __shfl_xor_sync(0xffffffffu, a1, off);
        }
        if (lane == 0) { o[e] = a0 + b2v; o[e + wpt] = a1 + b2v; }
    }
    if (e < E) {
        const int u0 = __ldg(uu + e), v0 = __ldg(vv + e);
        uint4 pr0 = *(const uint4*)(P + (size_t)u0 * HID + lane * 8);
        uint4 qr0 = *(const uint4*)(Q + (size_t)v0 * HID + lane * 8);
        float a0 = dot8(pr0, qr0);
        #pragma unroll
        for (int off = 16; off; off >>= 1)
            a0 += __shfl_xor_sync(0xffffffffu, a0, off);
        if (lane == 0) o[e] = a0 + b2v;
    }
}

// ---------------------------------------------------------------------------
extern "C" void kernel_launch(void* const* d_in, const int* in_sizes, int n_in,
                              void* d_out, int out_size) {
    const float* user_embed = (const float*)d_in[0];
    const float* item_embed = (const float*)d_in[1];
    const int*   u_clicks   = (const int*)  d_in[2];
    const int*   v_clicks   = (const int*)  d_in[3];
    const int*   u_buys     = (const int*)  d_in[4];
    const int*   v_buys     = (const int*)  d_in[5];
    const float* W1_clicks  = (const float*)d_in[6];
    const float* b1_clicks  = (const float*)d_in[7];
    const float* W2_clicks  = (const float*)d_in[8];
    const float* b2_clicks  = (const float*)d_in[9];
    const float* W1_buys    = (const float*)d_in[10];
    const float* b1_buys    = (const float*)d_in[11];
    const float* W2_buys    = (const float*)d_in[12];
    const float* b2_buys    = (const float*)d_in[13];

    const int E = in_sizes[2];
    float* out = (float*)d_out;

    __half* tab = nullptr;
    cudaGetSymbolAddress((void**)&tab, g_tab);
    __half* Pc = tab;
    __half* Qc = Pc + P_ELEMS;
    __half* Pb = Qc + Q_ELEMS;
    __half* Qb = Pb + P_ELEMS;

    __half* wext = nullptr;
    cudaGetSymbolAddress((void**)&wext, g_wext);

    static bool attr_set = false;
    if (!attr_set) {
        cudaFuncSetAttribute(gemm_kernel,
                             cudaFuncAttributeMaxDynamicSharedMemorySize, GEMM_SMEM);
        attr_set = true;
    }

    const size_t wstride = (size_t)HID * IN_DIM;
    convW_kernel<<<dim3(16, 4), 256>>>(W1_clicks, W1_buys, wext);

    const int gU = NTILE_U < 148 ? NTILE_U : 148;
    const int gI = NTILE_I < 148 ? NTILE_I : 148;
    gemm_kernel<<<gU, 512, GEMM_SMEM>>>(user_embed, NTILE_U, NU,
                                        wext + 0 * wstride, wext + 2 * wstride,
                                        b1_clicks, b1_buys, Pc, Pb);
    gemm_kernel<<<gI, 512, GEMM_SMEM>>>(item_embed, NTILE_I, NI,
                                        wext + 1 * wstride, wext + 3 * wstride,
                                        b1_clicks, b1_buys, Qc, Qb);

    const int eblocks = 740;                       // 5 CTAs/SM
    const int wpt = eblocks * 8 / 2;               // 2960 warps per task
    edge_kernel<<<eblocks, 256>>>(u_clicks, v_clicks, u_buys, v_buys,
                                  Pc, Qc, Pb, Qb,
                                  (const float4*)W2_clicks, b2_clicks,
                                  (const float4*)W2_buys, b2_buys,
                                  out, E, wpt);
}

// round 17
// speedup vs baseline: 1.9269x; 1.1039x over previous
#include <cuda_runtime.h>
#include <cuda_bf16.h>
#include <cuda_fp16.h>
#include <cstdint>

#define IN_DIM 128
#define HID    256
#define NU 100000
#define NI 200000
#define NTILE_U ((NU + 127) / 128)   // 782
#define NTILE_I ((NI + 127) / 128)   // 1563
#define NTILES  (NTILE_U + NTILE_I)  // 2345

#define P_ELEMS (100000u * 256u)
#define Q_ELEMS (200000u * 256u)
__device__ __half g_tab[2u * (P_ELEMS + Q_ELEMS)];
__device__ __align__(16) __half g_wext[4][HID * IN_DIM];   // fp16 W, [n][k]

// ---------------------------------------------------------------------------
__device__ __forceinline__ uint32_t smem_u32(const void* p) {
    uint32_t a;
    asm("{ .reg .u64 t; cvta.to.shared.u64 t, %1; cvt.u32.u64 %0, t; }"
        : "=r"(a) : "l"(p));
    return a;
}
__device__ __forceinline__ uint32_t swz(uint32_t o) { return o ^ ((o >> 3) & 0x70); }
template <int N>
__device__ __forceinline__ void cpwait() {
    asm volatile("cp.async.wait_group %0;" :: "n"(N) : "memory");
}

// ---------------------------------------------------------------------------
// convW: 4 combos in one launch; W-half [128 k][256 n] fp32 -> fp16 [n][k]
// combo = task*2 + table  (0: user-clicks, 1: item-clicks, 2: user-buys, 3: item-buys)
// ---------------------------------------------------------------------------
__global__ __launch_bounds__(256)
void convW_kernel(const float* __restrict__ Wc, const float* __restrict__ Wb,
                  __half* __restrict__ wext) {
    const int combo = blockIdx.y;
    const float* Wsrc = ((combo < 2) ? Wc : Wb) + (size_t)(combo & 1) * IN_DIM * HID;
    __half* Wext = wext + (size_t)combo * HID * IN_DIM;
    for (int idx = blockIdx.x * 256 + threadIdx.x; idx < HID * IN_DIM;
         idx += gridDim.x * 256) {
        const int n = idx >> 7, k = idx & 127;
        Wext[(size_t)n * IN_DIM + k] = __float2half_rn(Wsrc[(size_t)k * HID + n]);
    }
}

// ---------------------------------------------------------------------------
// ONE persistent gemm over all user+item tiles. Single-pass fp16.
// Per tile: 4 chunk-iterations = 2 tasks x 2 W-chunks. B triple-buffered
// (global mod-3 cursor). b1 for both tasks cached in smem.
// smem: Astage fp32 64KB | Aconv fp16 32KB | B0|B1|B2 3x32KB | b1 2KB.
// ---------------------------------------------------------------------------
#define KC 64
#define SM_STAGE 0
#define SM_ACONV 65536
#define SM_B_OFF (65536 + 32768)
#define SM_B1    (SM_B_OFF + 3 * 32768)
#define GEMM_SMEM (SM_B1 + 2048)

__device__ __forceinline__ void ldsm4(uint32_t* r, uint32_t a) {
    asm volatile("ldmatrix.sync.aligned.m8n8.x4.shared.b16 {%0,%1,%2,%3}, [%4];"
                 : "=r"(r[0]), "=r"(r[1]), "=r"(r[2]), "=r"(r[3]) : "r"(a));
}
__device__ __forceinline__ void mma16816(float* d, const uint32_t* a, const uint32_t* b) {
    asm volatile("mma.sync.aligned.m16n8k16.row.col.f32.f16.f16.f32 "
                 "{%0,%1,%2,%3}, {%4,%5,%6,%7}, {%8,%9}, {%0,%1,%2,%3};"
                 : "+f"(d[0]), "+f"(d[1]), "+f"(d[2]), "+f"(d[3])
                 : "r"(a[0]), "r"(a[1]), "r"(a[2]), "r"(a[3]), "r"(b[0]), "r"(b[1]));
}

__global__ __launch_bounds__(512, 1)
void gemm_kernel(const float* __restrict__ Auser, const float* __restrict__ Aitem,
                 const __half* __restrict__ wext,
                 const float* __restrict__ b1_0, const float* __restrict__ b1_1,
                 __half* __restrict__ Pc, __half* __restrict__ Pb,
                 __half* __restrict__ Qc, __half* __restrict__ Qb) {
    extern __shared__ __align__(1024) unsigned char sm[];
    const uint32_t sbase = smem_u32(sm);
    const int tid  = threadIdx.x;
    const int lane = tid & 31;
    const int wid  = tid >> 5;
    const int wm   = wid & 3;
    const int wn   = wid >> 2;
    const size_t wstride = (size_t)HID * IN_DIM;

    // b1 of both tasks -> smem (2KB), once per CTA
    if (tid < 256) *(float*)(sm + SM_B1 + tid * 4)        = b1_0[tid];
    else           *(float*)(sm + SM_B1 + 1024 + (tid - 256) * 4) = b1_1[tid - 256];

    // B chunk cc (0..3: task=cc>>1, k-chunk=cc&1) of tile `tile` -> buffer buf
    auto issue_b = [&](int cc, int buf, int tile) {
        const int combo = ((cc >> 1) << 1) + (tile >= NTILE_U ? 1 : 0);
        const char* Bb = (const char*)(wext + (size_t)combo * wstride);
        const int c = cc & 1;
        const uint32_t sb = sbase + SM_B_OFF + (uint32_t)buf * 32768;
        #pragma unroll
        for (int i = 0; i < 4; i++) {
            const int idx = tid + i * 512;
            const int r = idx >> 3, s = idx & 7;
            const size_t go = (size_t)r * (IN_DIM * 2) + c * (KC * 2) + s * 16;
            const uint32_t so = swz((uint32_t)(r * 128 + s * 16));
            asm volatile("cp.async.cg.shared.global [%0], [%1], 16;"
                         :: "r"(sb + so), "l"(Bb + go) : "memory");
        }
        asm volatile("cp.async.commit_group;" ::: "memory");
    };
    auto issue_a = [&](int tile) {
        const bool itm = (tile >= NTILE_U);
        const int lt = itm ? tile - NTILE_U : tile;
        const int Nloc = itm ? NI : NU;
        const float* Ab = (itm ? Aitem : Auser) + (size_t)lt * 128 * IN_DIM;
        const uint32_t sa = sbase + SM_STAGE;
        #pragma unroll
        for (int i = 0; i < 8; i++) {
            const int idx = tid + i * 512;
            const int r = idx >> 5, s = idx & 31;
            const int rg = lt * 128 + r;
            const uint32_t so = (uint32_t)(r * 512 + s * 16);
            if (rg < Nloc) {
                asm volatile("cp.async.cg.shared.global [%0], [%1], 16;"
                             :: "r"(sa + so), "l"((const char*)Ab + (size_t)r * 512 + s * 16)
                             : "memory");
            } else {
                *(uint4*)(sm + SM_STAGE + so) = make_uint4(0, 0, 0, 0);
            }
        }
        asm volatile("cp.async.commit_group;" ::: "memory");
    };
    auto convert_a = [&]() {
        #pragma unroll
        for (int i = 0; i < 8; i++) {
            const int idx = tid + i * 512;
            const int r = idx >> 5, c4 = idx & 31;
            float4 v = *(float4*)(sm + SM_STAGE + r * 512 + c4 * 16);
            __half2 h01 = __floats2half2_rn(v.x, v.y);
            __half2 h23 = __floats2half2_rn(v.z, v.w);
            uint2 uh = { *(uint32_t*)&h01, *(uint32_t*)&h23 };
            const uint32_t ck = (uint32_t)(c4 >> 4);
            const uint32_t off = swz((uint32_t)(r * 128 + (c4 & 15) * 8));
            *(uint2*)(sm + SM_ACONV + ck * 16384 + off) = uh;
        }
    };

    float acc[2][8][4];
    #pragma unroll
    for (int mt = 0; mt < 2; mt++)
        #pragma unroll
        for (int nt = 0; nt < 8; nt++)
            #pragma unroll
            for (int j = 0; j < 4; j++) acc[mt][nt][j] = 0.f;

    const int t0 = blockIdx.x;
    if (t0 >= NTILES) return;

    issue_a(t0);
    issue_b(0, 0, t0);
    int bcur = 0;   // global mod-3 B-buffer cursor (carried across tiles)

    const int amap[4] = {0, 1, 0, 1};

    for (int t = t0; t < NTILES; t += gridDim.x) {
        const int tnext = t + gridDim.x;
        const bool a_iss = (tnext < NTILES);
        const bool itm = (t >= NTILE_U);
        const int lt = itm ? t - NTILE_U : t;
        const int Nloc = itm ? NI : NU;
        __half* Pt0 = itm ? Qc : Pc;
        __half* Pt1 = itm ? Qb : Pb;

        cpwait<1>();          // A(t) complete; B(chunk 0) may still be in flight
        __syncthreads();
        convert_a();
        __syncthreads();

        #pragma unroll
        for (int c = 0; c < 4; c++) {
            const bool last_all = (c == 3) && !a_iss;
            if (!last_all) {
                const int nb = (bcur + 1 == 3) ? 0 : bcur + 1;
                if (c == 3) issue_b(0, nb, tnext);
                else        issue_b(c + 1, nb, t);
            }
            if (c == 0 && a_iss) issue_a(tnext);

            if (last_all)              cpwait<0>();
            else if (c < 2 && a_iss)   cpwait<2>();
            else                       cpwait<1>();
            __syncthreads();          // the only barrier per iteration

            const uint32_t sa = sbase + SM_ACONV + (uint32_t)(amap[c] * 16384);
            const uint32_t sb = sbase + SM_B_OFF + (uint32_t)(bcur * 32768);

            #pragma unroll
            for (int ks = 0; ks < KC / 16; ks++) {
                uint32_t af[2][4];
                #pragma unroll
                for (int mt = 0; mt < 2; mt++) {
                    const int row = wm * 32 + mt * 16 + (lane & 15);
                    const uint32_t off = (uint32_t)(row * 128 + ks * 32 + (lane >> 4) * 16);
                    ldsm4(af[mt], sa + swz(off));
                }
                uint32_t bfr[8][2];
                #pragma unroll
                for (int ntp = 0; ntp < 4; ntp++) {
                    const int nrow = wn * 64 + ntp * 16 + ((lane >> 4) << 3) + (lane & 7);
                    const uint32_t off = (uint32_t)(nrow * 128 + ks * 32 + ((lane >> 3) & 1) * 16);
                    uint32_t r4[4];
                    ldsm4(r4, sb + swz(off));
                    bfr[2 * ntp][0] = r4[0]; bfr[2 * ntp][1] = r4[1];
                    bfr[2 * ntp + 1][0] = r4[2]; bfr[2 * ntp + 1][1] = r4[3];
                }
                #pragma unroll
                for (int mt = 0; mt < 2; mt++)
                    #pragma unroll
                    for (int nt = 0; nt < 8; nt++)
                        mma16816(acc[mt][nt], af[mt], bfr[nt]);
            }
            // no trailing barrier (triple-buffered B)

            if (c == 1 || c == 3) {
                __half* Pt = (c == 1) ? Pt0 : Pt1;
                const uint32_t b1s = sbase + SM_B1 + ((c == 1) ? 0u : 1024u);
                const int rb = lt * 128 + wm * 32 + (lane >> 2);
                const int cb = wn * 64 + (lane & 3) * 2;
                #pragma unroll
                for (int mt = 0; mt < 2; mt++) {
                    #pragma unroll
                    for (int hf = 0; hf < 2; hf++) {
                        const int r = rb + mt * 16 + hf * 8;
                        if (r < Nloc) {
                            __half* dst = Pt + (size_t)r * HID + cb;
                            #pragma unroll
                            for (int nt = 0; nt < 8; nt++) {
                                const int cc2 = cb + nt * 8;
                                float2 bv = *(float2*)(sm + (b1s - sbase) + cc2 * 4);
                                float a0 = acc[mt][nt][hf * 2]     + bv.x;
                                float a1 = acc[mt][nt][hf * 2 + 1] + bv.y;
                                *(__half2*)(dst + nt * 8) = __floats2half2_rn(a0, a1);
                            }
                        }
                    }
                }
                #pragma unroll
                for (int mt = 0; mt < 2; mt++)
                    #pragma unroll
                    for (int nt = 0; nt < 8; nt++)
                        #pragma unroll
                        for (int j = 0; j < 4; j++) acc[mt][nt][j] = 0.f;
            }
            bcur = (bcur + 1 == 3) ? 0 : bcur + 1;
        }
    }
}

// ---------------------------------------------------------------------------
// edge (unchanged): persistent warps; W2/b2 in registers; 2 edges in flight.
// ---------------------------------------------------------------------------
__global__ __launch_bounds__(256)
void edge_kernel(const int* __restrict__ uc, const int* __restrict__ vc,
                 const int* __restrict__ ub, const int* __restrict__ vb,
                 const __half* __restrict__ Pc, const __half* __restrict__ Qc,
                 const __half* __restrict__ Pb, const __half* __restrict__ Qb,
                 const float4* __restrict__ W2c, const float* __restrict__ b2c,
                 const float4* __restrict__ W2b, const float* __restrict__ b2b,
                 float* __restrict__ out, int E, int wpt) {
    const int gw   = (blockIdx.x * blockDim.x + threadIdx.x) >> 5;
    const int lane = threadIdx.x & 31;
    const bool buys = (gw >= wpt);
    const int w0 = buys ? gw - wpt : gw;

    const int* uu = buys ? ub : uc;
    const int* vv = buys ? vb : vc;
    const __half* P = buys ? Pb : Pc;
    const __half* Q = buys ? Qb : Qc;
    const float4* W2 = buys ? W2b : W2c;
    float* o = out + (buys ? E : 0);

    float4 wv0 = __ldg(W2 + lane * 2);
    float4 wv1 = __ldg(W2 + lane * 2 + 1);
    const float b2v = __ldg(buys ? b2b : b2c);
    float w[8] = { wv0.x, wv0.y, wv0.z, wv0.w, wv1.x, wv1.y, wv1.z, wv1.w };

    auto dot8 = [&](const uint4& pr, const uint4& qr) -> float {
        const __half2* p2 = (const __half2*)&pr;
        const __half2* q2 = (const __half2*)&qr;
        float a = 0.f;
        #pragma unroll
        for (int i = 0; i < 4; i++) {
            float2 pf = __half22float2(p2[i]);
            float2 qf = __half22float2(q2[i]);
            a = fmaf(fmaxf(pf.x + qf.x, 0.f), w[2 * i],     a);
            a = fmaf(fmaxf(pf.y + qf.y, 0.f), w[2 * i + 1], a);
        }
        return a;
    };

    int e = w0;
    for (; e + wpt < E; e += 2 * wpt) {
        const int u0 = __ldg(uu + e),       v0 = __ldg(vv + e);
        const int u1 = __ldg(uu + e + wpt), v1 = __ldg(vv + e + wpt);
        uint4 pr0 = *(const uint4*)(P + (size_t)u0 * HID + lane * 8);
        uint4 qr0 = *(const uint4*)(Q + (size_t)v0 * HID + lane * 8);
        uint4 pr1 = *(const uint4*)(P + (size_t)u1 * HID + lane * 8);
        uint4 qr1 = *(const uint4*)(Q + (size_t)v1 * HID + lane * 8);
        float a0 = dot8(pr0, qr0);
        float a1 = dot8(pr1, qr1);
        #pragma unroll
        for (int off = 16; off; off >>= 1) {
            a0 += __shfl_xor_sync(0xffffffffu, a0, off);
            a1 += __shfl_xor_sync(0xffffffffu, a1, off);
        }
        if (lane == 0) { o[e] = a0 + b2v; o[e + wpt] = a1 + b2v; }
    }
    if (e < E) {
        const int u0 = __ldg(uu + e), v0 = __ldg(vv + e);
        uint4 pr0 = *(const uint4*)(P + (size_t)u0 * HID + lane * 8);
        uint4 qr0 = *(const uint4*)(Q + (size_t)v0 * HID + lane * 8);
        float a0 = dot8(pr0, qr0);
        #pragma unroll
        for (int off = 16; off; off >>= 1)
            a0 += __shfl_xor_sync(0xffffffffu, a0, off);
        if (lane == 0) o[e] = a0 + b2v;
    }
}

// ---------------------------------------------------------------------------
extern "C" void kernel_launch(void* const* d_in, const int* in_sizes, int n_in,
                              void* d_out, int out_size) {
    const float* user_embed = (const float*)d_in[0];
    const float* item_embed = (const float*)d_in[1];
    const int*   u_clicks   = (const int*)  d_in[2];
    const int*   v_clicks   = (const int*)  d_in[3];
    const int*   u_buys     = (const int*)  d_in[4];
    const int*   v_buys     = (const int*)  d_in[5];
    const float* W1_clicks  = (const float*)d_in[6];
    const float* b1_clicks  = (const float*)d_in[7];
    const float* W2_clicks  = (const float*)d_in[8];
    const float* b2_clicks  = (const float*)d_in[9];
    const float* W1_buys    = (const float*)d_in[10];
    const float* b1_buys    = (const float*)d_in[11];
    const float* W2_buys    = (const float*)d_in[12];
    const float* b2_buys    = (const float*)d_in[13];

    const int E = in_sizes[2];
    float* out = (float*)d_out;

    __half* tab = nullptr;
    cudaGetSymbolAddress((void**)&tab, g_tab);
    __half* Pc = tab;
    __half* Qc = Pc + P_ELEMS;
    __half* Pb = Qc + Q_ELEMS;
    __half* Qb = Pb + P_ELEMS;

    __half* wext = nullptr;
    cudaGetSymbolAddress((void**)&wext, g_wext);

    static bool attr_set = false;
    if (!attr_set) {
        cudaFuncSetAttribute(gemm_kernel,
                             cudaFuncAttributeMaxDynamicSharedMemorySize, GEMM_SMEM);
        attr_set = true;
    }

    convW_kernel<<<dim3(16, 4), 256>>>(W1_clicks, W1_buys, wext);

    gemm_kernel<<<148, 512, GEMM_SMEM>>>(user_embed, item_embed, wext,
                                         b1_clicks, b1_buys,
                                         Pc, Pb, Qc, Qb);

    const int eblocks = 740;                       // 5 CTAs/SM
    const int wpt = eblocks * 8 / 2;               // 2960 warps per task
    edge_kernel<<<eblocks, 256>>>(u_clicks, v_clicks, u_buys, v_buys,
                                  Pc, Qc, Pb, Qb,
                                  (const float4*)W2_clicks, b2_clicks,
                                  (const float4*)W2_buys, b2_buys,
                                  out, E, wpt);
}